// round 12
// baseline (speedup 1.0000x reference)
#include <cuda_runtime.h>
#include <cuda_bf16.h>
#include <cuda_fp16.h>
#include <cstdint>

#define NNODES 100000
#define NEDGES 800000
#define DIM 128

// ---------------- static scratch ----------------
__device__ __align__(16) float g_z[(size_t)NNODES * DIM];               // z fp32 (final layer)
__device__ __align__(16) __half g_zh[(size_t)NNODES * DIM];             // z fp16 (layers 0,1)
__device__ __align__(16) __half g_hx[(size_t)NNODES * DIM];             // x staged fp16
__device__ __align__(16) __nv_bfloat16 g_as[(size_t)NNODES * 2 * DIM];  // [N][256] hi|lo
__device__ __align__(16) __nv_bfloat16 g_wt[6 * 128 * 256];             // [l*2+m][n][256] hi|lo
__device__ float g_stats[3 * 256];                                      // per-layer colsum|colsumsq
__device__ int g_deg[NNODES];
__device__ int g_rowptr[NNODES];
__device__ int g_cursor[NNODES];
__device__ int g_eidx[NEDGES];
__device__ int g_part[512];
__device__ int g_is64;

// ---------------- edge dtype detection (jax x64 trap) ----------------
__global__ void detect_kernel(const void* __restrict__ ei, int E, int n) {
    __shared__ int bad;
    if (threadIdx.x == 0) bad = 0;
    __syncthreads();
    const long long* p = (const long long*)ei;
    int m = (E < 4096) ? E : 4096;
    for (int i = threadIdx.x; i < m; i += blockDim.x) {
        long long v = p[i];
        if (v < 0 || v >= (long long)n) bad = 1;
    }
    __syncthreads();
    if (threadIdx.x == 0) g_is64 = bad ? 0 : 1;
}

__device__ __forceinline__ int load_idx(const void* ei, int is64, size_t pos) {
    if (is64) return (int)((const long long*)ei)[pos];
    return ((const int*)ei)[pos];
}

// ---------------- weight prep ----------------
__global__ void wprep_kernel(const float* __restrict__ W1, const float* __restrict__ W2) {
    int idx = blockIdx.x * blockDim.x + threadIdx.x;
    if (idx >= 3 * 2 * 128 * 128) return;
    int n = idx & 127;
    int k = (idx >> 7) & 127;
    int m = (idx >> 14) & 1;
    int l = idx >> 15;
    const float* W = m ? W2 : W1;
    float v = W[((size_t)l * 128 + k) * 128 + n];
    __nv_bfloat16 hi = __float2bfloat16(v);
    __nv_bfloat16 lo = __float2bfloat16(v - __bfloat162float(hi));
    size_t base = ((size_t)(l * 2 + m) * 128 + n) * 256;
    g_wt[base + k] = hi;
    g_wt[base + 128 + k] = lo;
}

// ---------------- x -> fp16 staging; zero degree counters + stats slots ----------------
__global__ void prepx_kernel(const float* __restrict__ x, int n) {
    int idx = blockIdx.x * blockDim.x + threadIdx.x;
    if (idx < n) g_deg[idx] = 0;
    if (idx < 3 * 256) g_stats[idx] = 0.f;
    if (idx >= n * 32) return;
    int row = idx >> 5;
    int c4 = (idx & 31) * 4;
    float4 v = *reinterpret_cast<const float4*>(x + (size_t)row * DIM + c4);
    __half2 a = __floats2half2_rn(v.x, v.y);
    __half2 b = __floats2half2_rn(v.z, v.w);
    *reinterpret_cast<__half2*>(g_hx + (size_t)row * DIM + c4) = a;
    *reinterpret_cast<__half2*>(g_hx + (size_t)row * DIM + c4 + 2) = b;
}

// ---------------- CSR build ----------------
__global__ void hist_kernel(const void* __restrict__ ei, int E, int n) {
    int e = blockIdx.x * blockDim.x + threadIdx.x;
    if (e >= E) return;
    int d = load_idx(ei, g_is64, (size_t)E + e);
    if ((unsigned)d < (unsigned)n) atomicAdd(&g_deg[d], 1);
}

__global__ void scanA_kernel(int n) {
    __shared__ int s[512];
    int tid = threadIdx.x;
    int i = blockIdx.x * 512 + tid;
    s[tid] = (i < n) ? g_deg[i] : 0;
    __syncthreads();
    for (int off = 256; off > 0; off >>= 1) {
        if (tid < off) s[tid] += s[tid + off];
        __syncthreads();
    }
    if (tid == 0) g_part[blockIdx.x] = s[0];
}

__global__ void scanB_kernel(int nb) {
    __shared__ int s[512];
    int tid = threadIdx.x;
    int v = (tid < nb) ? g_part[tid] : 0;
    s[tid] = v;
    __syncthreads();
    for (int off = 1; off < 512; off <<= 1) {
        int tv = (tid >= off) ? s[tid - off] : 0;
        __syncthreads();
        s[tid] += tv;
        __syncthreads();
    }
    if (tid < nb) g_part[tid] = s[tid] - v;   // exclusive
}

__global__ void scanC_kernel(int n) {
    __shared__ int s[512];
    int tid = threadIdx.x;
    int i = blockIdx.x * 512 + tid;
    int v = (i < n) ? g_deg[i] : 0;
    s[tid] = v;
    __syncthreads();
    for (int off = 1; off < 512; off <<= 1) {
        int tv = (tid >= off) ? s[tid - off] : 0;
        __syncthreads();
        s[tid] += tv;
        __syncthreads();
    }
    if (i < n) {
        int start = g_part[blockIdx.x] + s[tid] - v;
        g_rowptr[i] = start;
        g_cursor[i] = start;
    }
}

__global__ void fill_kernel(const void* __restrict__ ei, int E, int n) {
    int e = blockIdx.x * blockDim.x + threadIdx.x;
    if (e >= E) return;
    int is64 = g_is64;
    int s = load_idx(ei, is64, (size_t)e);
    int d = load_idx(ei, is64, (size_t)E + e);
    if ((unsigned)d >= (unsigned)n || (unsigned)s >= (unsigned)n) return;
    int pos = atomicAdd(&g_cursor[d], 1);
    g_eidx[pos] = s;
}

// ---------------- fused gather: (BN+ReLU) + aggregate + hi/lo split ----------------
// BN==1: reads fp16 z from layer (layer-1), computes its own 2 BN coefficient
// columns inline from the stats slot (2 rsqrtf/thread — trivial).
template <int BN>
__global__ __launch_bounds__(256) void gather_kernel(const float* __restrict__ gamma,
                                                     const float* __restrict__ beta,
                                                     int slot, int n) {
    int gidx = blockIdx.x * blockDim.x + threadIdx.x;
    int wid = gidx >> 5;
    int node = wid >> 1;
    if (node >= n) return;
    int half = wid & 1;
    int lane = gidx & 31;
    int col = half * 64 + lane * 2;

    const __half* __restrict__ hsrc = BN ? (const __half*)g_zh : (const __half*)g_hx;

    float2 sc, sh;
    if (BN) {
        const float* st = g_stats + slot * 256;
        float invN = 1.f / (float)n;
        float m0 = st[col] * invN;
        float m1 = st[col + 1] * invN;
        float v0 = st[128 + col] * invN - m0 * m0;
        float v1 = st[128 + col + 1] * invN - m1 * m1;
        float r0 = rsqrtf(fmaxf(v0, 0.f) + 1e-5f);
        float r1 = rsqrtf(fmaxf(v1, 0.f) + 1e-5f);
        sc.x = gamma[col] * r0;     sc.y = gamma[col + 1] * r1;
        sh.x = beta[col] - m0 * sc.x;
        sh.y = beta[col + 1] - m1 * sc.y;
    }

    float2 v = __half22float2(*reinterpret_cast<const __half2*>(hsrc + (size_t)node * DIM + col));
    float ax, ay;
    if (BN) {
        ax = fmaxf(v.x * sc.x + sh.x, 0.f);
        ay = fmaxf(v.y * sc.y + sh.y, 0.f);
    } else {
        ax = v.x; ay = v.y;
    }

    int j = g_rowptr[node];
    int end = j + g_deg[node];
    for (; j + 4 <= end; j += 4) {
        int s0 = g_eidx[j], s1 = g_eidx[j + 1], s2 = g_eidx[j + 2], s3 = g_eidx[j + 3];
        float2 u0 = __half22float2(*reinterpret_cast<const __half2*>(hsrc + (size_t)s0 * DIM + col));
        float2 u1 = __half22float2(*reinterpret_cast<const __half2*>(hsrc + (size_t)s1 * DIM + col));
        float2 u2 = __half22float2(*reinterpret_cast<const __half2*>(hsrc + (size_t)s2 * DIM + col));
        float2 u3 = __half22float2(*reinterpret_cast<const __half2*>(hsrc + (size_t)s3 * DIM + col));
        if (BN) {
            ax += fmaxf(u0.x * sc.x + sh.x, 0.f) + fmaxf(u1.x * sc.x + sh.x, 0.f)
                + fmaxf(u2.x * sc.x + sh.x, 0.f) + fmaxf(u3.x * sc.x + sh.x, 0.f);
            ay += fmaxf(u0.y * sc.y + sh.y, 0.f) + fmaxf(u1.y * sc.y + sh.y, 0.f)
                + fmaxf(u2.y * sc.y + sh.y, 0.f) + fmaxf(u3.y * sc.y + sh.y, 0.f);
        } else {
            ax += u0.x + u1.x + u2.x + u3.x;
            ay += u0.y + u1.y + u2.y + u3.y;
        }
    }
    for (; j < end; j++) {
        int s = g_eidx[j];
        float2 u = __half22float2(*reinterpret_cast<const __half2*>(hsrc + (size_t)s * DIM + col));
        if (BN) {
            ax += fmaxf(u.x * sc.x + sh.x, 0.f);
            ay += fmaxf(u.y * sc.y + sh.y, 0.f);
        } else {
            ax += u.x; ay += u.y;
        }
    }

    __nv_bfloat16 h0 = __float2bfloat16(ax);
    __nv_bfloat16 h1 = __float2bfloat16(ay);
    __nv_bfloat16 l0 = __float2bfloat16(ax - __bfloat162float(h0));
    __nv_bfloat16 l1 = __float2bfloat16(ay - __bfloat162float(h1));
    union { __nv_bfloat162 b; uint32_t u; } HP, LP;
    HP.b.x = h0; HP.b.y = h1; LP.b.x = l0; LP.b.y = l1;
    __nv_bfloat16* op = g_as + (size_t)node * 256 + col;
    *reinterpret_cast<uint32_t*>(op) = HP.u;
    *reinterpret_cast<uint32_t*>(op + 128) = LP.u;
}

// ---------------- persistent fused MLP ----------------
#define ASTRIDE 264
#define WBYTES (128 * ASTRIDE * 2)
#define ABYTES (64 * ASTRIDE * 2)
#define SMEM_BYTES (2 * WBYTES + 2 * ABYTES)
#define MLP_GRID 148

__device__ __forceinline__ void mma_bf16(float d[4], const uint32_t a[4], const uint32_t b0, const uint32_t b1) {
    asm volatile(
        "mma.sync.aligned.m16n8k16.row.col.f32.bf16.bf16.f32 "
        "{%0,%1,%2,%3}, {%4,%5,%6,%7}, {%8,%9}, {%0,%1,%2,%3};\n"
        : "+f"(d[0]), "+f"(d[1]), "+f"(d[2]), "+f"(d[3])
        : "r"(a[0]), "r"(a[1]), "r"(a[2]), "r"(a[3]), "r"(b0), "r"(b1));
}

__device__ __forceinline__ void ldsm_x4(uint32_t r[4], uint32_t addr) {
    asm volatile("ldmatrix.sync.aligned.m8n8.x4.shared.b16 {%0,%1,%2,%3}, [%4];\n"
                 : "=r"(r[0]), "=r"(r[1]), "=r"(r[2]), "=r"(r[3]) : "r"(addr));
}

__device__ __forceinline__ void cpa16(uint32_t dst, const void* src) {
    asm volatile("cp.async.ca.shared.global [%0], [%1], 16;\n" :: "r"(dst), "l"(src));
}

// fused 3-pass k-loop; warp tile 16x32: 6 LDSM + 12 MMA per k-step
__device__ __forceinline__ void gemm_phase(uint32_t aAddr, const uint32_t bAddr0, const uint32_t bAddr1,
                                           float acc[4][4]) {
    uint32_t bA[2] = {bAddr0, bAddr1};
#pragma unroll
    for (int kk = 0; kk < 128; kk += 16) {
        uint32_t ah[4], al[4], bh[2][4], bl[2][4];
        ldsm_x4(ah, aAddr + kk * 2);
        ldsm_x4(al, aAddr + 256 + kk * 2);
#pragma unroll
        for (int np = 0; np < 2; np++) {
            ldsm_x4(bh[np], bA[np] + kk * 2);
            ldsm_x4(bl[np], bA[np] + 256 + kk * 2);
        }
#pragma unroll
        for (int nt = 0; nt < 4; nt++)
            mma_bf16(acc[nt], ah, bh[nt >> 1][(nt & 1) * 2], bh[nt >> 1][(nt & 1) * 2 + 1]);
#pragma unroll
        for (int nt = 0; nt < 4; nt++)
            mma_bf16(acc[nt], ah, bl[nt >> 1][(nt & 1) * 2], bl[nt >> 1][(nt & 1) * 2 + 1]);
#pragma unroll
        for (int nt = 0; nt < 4; nt++)
            mma_bf16(acc[nt], al, bh[nt >> 1][(nt & 1) * 2], bh[nt >> 1][(nt & 1) * 2 + 1]);
    }
}

// LAST=0: z -> g_zh (fp16, read by next gather). LAST=1: z -> g_z (fp32, read by
// bnfinal — keeps the direct output path free of fp16 rounding).
template <int LAST>
__global__ __launch_bounds__(512, 1) void mlp_kernel(int layer, const float* __restrict__ b1,
                                                     const float* __restrict__ b2, int n) {
    extern __shared__ char smem_raw[];
    uint32_t sW1 = (uint32_t)__cvta_generic_to_shared(smem_raw);
    uint32_t sW2 = sW1 + WBYTES;
    uint32_t sA0 = sW2 + WBYTES;
    __shared__ float sb1[128], sb2[128], ssum[128], ssq[128];

    const __nv_bfloat16* __restrict__ W1g = g_wt + (size_t)(layer * 2 + 0) * 128 * 256;
    const __nv_bfloat16* __restrict__ W2g = g_wt + (size_t)(layer * 2 + 1) * 128 * 256;

    int tid = threadIdx.x;
    int numTiles = (n + 63) / 64;

    for (int i = tid; i < 4096; i += 512) {
        int r = i >> 5, s = i & 31;
        cpa16(sW1 + (r * ASTRIDE + s * 8) * 2, W1g + (size_t)r * 256 + s * 8);
        cpa16(sW2 + (r * ASTRIDE + s * 8) * 2, W2g + (size_t)r * 256 + s * 8);
    }
    {
        int tile = blockIdx.x;
        if (tile < numTiles) {
            int rb = tile * 64;
            for (int i = tid; i < 2048; i += 512) {
                int r = i >> 5, s = i & 31;
                int row = rb + r; if (row >= n) row = 0;
                cpa16(sA0 + (r * ASTRIDE + s * 8) * 2, g_as + (size_t)row * 256 + s * 8);
            }
        }
    }
    asm volatile("cp.async.commit_group;\n");
    if (tid < 128) { sb1[tid] = b1[tid]; sb2[tid] = b2[tid]; ssum[tid] = 0.f; ssq[tid] = 0.f; }

    int warp = tid >> 5, lane = tid & 31;
    int wm = warp & 3, wn = warp >> 2;          // 4(M) x 4(N) warp grid
    int mBase = wm * 16, nBase = wn * 32;       // warp tile 16 x 32
    int g = lane >> 2, t = lane & 3;
    int barid = 1 + wm;

    uint32_t aOff = (uint32_t)(((mBase + (lane & 15)) * ASTRIDE + (lane >> 4) * 8) * 2);
    uint32_t bOff0, bOff1;
    {
        int q = lane >> 3, rw = lane & 7;
        int rowoff = (q >> 1) * 8 + rw, coloff = (q & 1) * 8;
        bOff0 = (uint32_t)(((nBase + 0 + rowoff) * ASTRIDE + coloff) * 2);
        bOff1 = (uint32_t)(((nBase + 16 + rowoff) * ASTRIDE + coloff) * 2);
    }

    float cs[4][2], cq[4][2];
#pragma unroll
    for (int nt = 0; nt < 4; nt++) { cs[nt][0] = cs[nt][1] = 0.f; cq[nt][0] = cq[nt][1] = 0.f; }

    int buf = 0;
    for (int tile = blockIdx.x; tile < numTiles; tile += MLP_GRID) {
        asm volatile("cp.async.wait_group 0;\n" ::: "memory");
        __syncthreads();
        uint32_t sA = sA0 + buf * ABYTES;

        int next = tile + MLP_GRID;
        if (next < numTiles) {
            int rb = next * 64;
            uint32_t dstA = sA0 + (buf ^ 1) * ABYTES;
            for (int i = tid; i < 2048; i += 512) {
                int r = i >> 5, s = i & 31;
                int row = rb + r; if (row >= n) row = 0;
                cpa16(dstA + (r * ASTRIDE + s * 8) * 2, g_as + (size_t)row * 256 + s * 8);
            }
        }
        asm volatile("cp.async.commit_group;\n");

        // ---- GEMM 1 ----
        float acc[4][4];
#pragma unroll
        for (int b = 0; b < 4; b++)
#pragma unroll
            for (int c = 0; c < 4; c++) acc[b][c] = 0.f;
        gemm_phase(sA + aOff, sW1 + bOff0, sW1 + bOff1, acc);
        asm volatile("bar.sync %0, 128;" :: "r"(barid) : "memory");

        // epi 0: bias1 + relu + hi/lo split -> A[buf] rows of this group
#pragma unroll
        for (int i = 0; i < 2; i++) {
            int lrow = mBase + g + i * 8;
#pragma unroll
            for (int nt = 0; nt < 4; nt++) {
                int col = nBase + nt * 8 + t * 2;
                float v0 = fmaxf(acc[nt][i * 2 + 0] + sb1[col], 0.f);
                float v1 = fmaxf(acc[nt][i * 2 + 1] + sb1[col + 1], 0.f);
                __nv_bfloat16 h0 = __float2bfloat16(v0);
                __nv_bfloat16 h1 = __float2bfloat16(v1);
                __nv_bfloat16 l0 = __float2bfloat16(v0 - __bfloat162float(h0));
                __nv_bfloat16 l1 = __float2bfloat16(v1 - __bfloat162float(h1));
                union { __nv_bfloat162 b; uint32_t u; } HP, LP;
                HP.b.x = h0; HP.b.y = h1; LP.b.x = l0; LP.b.y = l1;
                uint32_t op = sA + (uint32_t)((lrow * ASTRIDE + col) * 2);
                asm volatile("st.shared.b32 [%0], %1;" :: "r"(op), "r"(HP.u));
                asm volatile("st.shared.b32 [%0], %1;" :: "r"(op + 256), "r"(LP.u));
            }
        }
        asm volatile("bar.sync %0, 128;" :: "r"(barid) : "memory");

        // ---- GEMM 2 ----
#pragma unroll
        for (int b = 0; b < 4; b++)
#pragma unroll
            for (int c = 0; c < 4; c++) acc[b][c] = 0.f;
        gemm_phase(sA + aOff, sW2 + bOff0, sW2 + bOff1, acc);

        // epi 1: bias2 -> z + register stats (fp32, unrounded)
        int rowBase = tile * 64;
#pragma unroll
        for (int i = 0; i < 2; i++) {
            int row = rowBase + mBase + g + i * 8;
            if (row >= n) continue;
#pragma unroll
            for (int nt = 0; nt < 4; nt++) {
                int col = nBase + nt * 8 + t * 2;
                float v0 = acc[nt][i * 2 + 0] + sb2[col];
                float v1 = acc[nt][i * 2 + 1] + sb2[col + 1];
                if (LAST) {
                    float2 zv; zv.x = v0; zv.y = v1;
                    *reinterpret_cast<float2*>(g_z + (size_t)row * DIM + col) = zv;
                } else {
                    *reinterpret_cast<__half2*>(g_zh + (size_t)row * DIM + col) = __floats2half2_rn(v0, v1);
                }
                cs[nt][0] += v0; cq[nt][0] += v0 * v0;
                cs[nt][1] += v1; cq[nt][1] += v1 * v1;
            }
        }
        buf ^= 1;
    }

    // final stats reduction: regs -> smem -> global slot (once per CTA)
    __syncthreads();
#pragma unroll
    for (int nt = 0; nt < 4; nt++) {
#pragma unroll
        for (int j = 0; j < 2; j++) {
            int col = nBase + nt * 8 + t * 2 + j;
            atomicAdd(&ssum[col], cs[nt][j]);
            atomicAdd(&ssq[col], cq[nt][j]);
        }
    }
    __syncthreads();
    if (tid < 128) {
        float* dst = g_stats + layer * 256;
        atomicAdd(&dst[tid], ssum[tid]);
        atomicAdd(&dst[128 + tid], ssq[tid]);
    }
}

// ---------------- final BN+ReLU -> d_out (reads fp32 z, inline BN coefficients) ----
__global__ void bnfinal_kernel(const float* __restrict__ gamma, const float* __restrict__ beta,
                               float* __restrict__ dout, int n) {
    int idx = blockIdx.x * blockDim.x + threadIdx.x;
    if (idx >= n * 32) return;
    int row = idx >> 5;
    int c4 = (idx & 31) * 4;
    const float* st = g_stats + 2 * 256;
    float invN = 1.f / (float)n;
    float4 z = *reinterpret_cast<const float4*>(g_z + (size_t)row * DIM + c4);
    float zz[4] = {z.x, z.y, z.z, z.w};
    float out[4];
#pragma unroll
    for (int j = 0; j < 4; j++) {
        int c = c4 + j;
        float mean = st[c] * invN;
        float var = st[128 + c] * invN - mean * mean;
        float rstd = rsqrtf(fmaxf(var, 0.f) + 1e-5f);
        out[j] = fmaxf(gamma[c] * (zz[j] - mean) * rstd + beta[c], 0.f);
    }
    float4 o; o.x = out[0]; o.y = out[1]; o.z = out[2]; o.w = out[3];
    *reinterpret_cast<float4*>(dout + (size_t)row * DIM + c4) = o;
}

// ---------------- host launcher ----------------
extern "C" void kernel_launch(void* const* d_in, const int* in_sizes, int n_in,
                              void* d_out, int out_size) {
    const float* x = (const float*)d_in[0];
    const void* ei = d_in[1];
    const float* W1 = (const float*)d_in[2];
    const float* b1 = (const float*)d_in[3];
    const float* W2 = (const float*)d_in[4];
    const float* b2 = (const float*)d_in[5];
    const float* gamma = (const float*)d_in[6];
    const float* beta = (const float*)d_in[7];
    (void)n_in; (void)out_size;

    int n = in_sizes[0] / DIM;
    int E = in_sizes[1] / 2;
    if (n > NNODES) n = NNODES;
    if (E > NEDGES) E = NEDGES;

    cudaFuncSetAttribute(mlp_kernel<0>, cudaFuncAttributeMaxDynamicSharedMemorySize, SMEM_BYTES);
    cudaFuncSetAttribute(mlp_kernel<1>, cudaFuncAttributeMaxDynamicSharedMemorySize, SMEM_BYTES);

    int gatherBlocks = (n * 64 + 255) / 256;   // 2 warps per node
    int ewBlocks = (n * 32 + 255) / 256;

    detect_kernel<<<1, 256>>>(ei, E, n);
    wprep_kernel<<<(3 * 2 * 128 * 128 + 255) / 256, 256>>>(W1, W2);
    prepx_kernel<<<ewBlocks, 256>>>(x, n);
    hist_kernel<<<(E + 255) / 256, 256>>>(ei, E, n);
    int nsb = (n + 511) / 512;
    scanA_kernel<<<nsb, 512>>>(n);
    scanB_kernel<<<1, 512>>>(nsb);
    scanC_kernel<<<nsb, 512>>>(n);
    fill_kernel<<<(E + 255) / 256, 256>>>(ei, E, n);

    for (int l = 0; l < 3; l++) {
        if (l == 0) gather_kernel<0><<<gatherBlocks, 256>>>(nullptr, nullptr, 0, n);
        else gather_kernel<1><<<gatherBlocks, 256>>>(gamma + (l - 1) * 128, beta + (l - 1) * 128, l - 1, n);
        if (l < 2) mlp_kernel<0><<<MLP_GRID, 512, SMEM_BYTES>>>(l, b1 + l * 128, b2 + l * 128, n);
        else mlp_kernel<1><<<MLP_GRID, 512, SMEM_BYTES>>>(l, b1 + l * 128, b2 + l * 128, n);
    }
    bnfinal_kernel<<<ewBlocks, 256>>>(gamma + 2 * 128, beta + 2 * 128, (float*)d_out, n);
}

// round 13
// speedup vs baseline: 1.0136x; 1.0136x over previous
#include <cuda_runtime.h>
#include <cuda_bf16.h>
#include <cuda_fp16.h>
#include <cstdint>

#define NNODES 100000
#define NEDGES 800000
#define DIM 128

// ---------------- static scratch ----------------
__device__ __align__(16) __half g_zh[(size_t)NNODES * DIM];             // z staged fp16 (all layers)
__device__ __align__(16) __half g_hx[(size_t)NNODES * DIM];             // x staged fp16
__device__ __align__(16) __nv_bfloat16 g_as[(size_t)NNODES * 2 * DIM];  // [N][256] hi|lo
__device__ __align__(16) __nv_bfloat16 g_wt[6 * 128 * 256];             // [l*2+m][n][256] hi|lo
__device__ float g_stats[3 * 256];                                      // per-layer colsum|colsumsq
__device__ int g_deg[NNODES];
__device__ int g_rowptr[NNODES];
__device__ int g_cursor[NNODES];
__device__ int g_eidx[NEDGES];
__device__ int g_part[512];
__device__ int g_is64;

// ---------------- edge dtype detection (jax x64 trap) ----------------
__global__ void detect_kernel(const void* __restrict__ ei, int E, int n) {
    __shared__ int bad;
    if (threadIdx.x == 0) bad = 0;
    __syncthreads();
    const long long* p = (const long long*)ei;
    int m = (E < 4096) ? E : 4096;
    for (int i = threadIdx.x; i < m; i += blockDim.x) {
        long long v = p[i];
        if (v < 0 || v >= (long long)n) bad = 1;
    }
    __syncthreads();
    if (threadIdx.x == 0) g_is64 = bad ? 0 : 1;
}

__device__ __forceinline__ int load_idx(const void* ei, int is64, size_t pos) {
    if (is64) return (int)((const long long*)ei)[pos];
    return ((const int*)ei)[pos];
}

// ---------------- weight prep ----------------
__global__ void wprep_kernel(const float* __restrict__ W1, const float* __restrict__ W2) {
    int idx = blockIdx.x * blockDim.x + threadIdx.x;
    if (idx >= 3 * 2 * 128 * 128) return;
    int n = idx & 127;
    int k = (idx >> 7) & 127;
    int m = (idx >> 14) & 1;
    int l = idx >> 15;
    const float* W = m ? W2 : W1;
    float v = W[((size_t)l * 128 + k) * 128 + n];
    __nv_bfloat16 hi = __float2bfloat16(v);
    __nv_bfloat16 lo = __float2bfloat16(v - __bfloat162float(hi));
    size_t base = ((size_t)(l * 2 + m) * 128 + n) * 256;
    g_wt[base + k] = hi;
    g_wt[base + 128 + k] = lo;
}

// ---------------- x -> fp16 staging; zero degree counters + stats slots ----------------
__global__ void prepx_kernel(const float* __restrict__ x, int n) {
    int idx = blockIdx.x * blockDim.x + threadIdx.x;
    if (idx < n) g_deg[idx] = 0;
    if (idx < 3 * 256) g_stats[idx] = 0.f;
    if (idx >= n * 32) return;
    int row = idx >> 5;
    int c4 = (idx & 31) * 4;
    float4 v = *reinterpret_cast<const float4*>(x + (size_t)row * DIM + c4);
    __half2 a = __floats2half2_rn(v.x, v.y);
    __half2 b = __floats2half2_rn(v.z, v.w);
    *reinterpret_cast<__half2*>(g_hx + (size_t)row * DIM + c4) = a;
    *reinterpret_cast<__half2*>(g_hx + (size_t)row * DIM + c4 + 2) = b;
}

// ---------------- CSR build ----------------
__global__ void hist_kernel(const void* __restrict__ ei, int E, int n) {
    int e = blockIdx.x * blockDim.x + threadIdx.x;
    if (e >= E) return;
    int d = load_idx(ei, g_is64, (size_t)E + e);
    if ((unsigned)d < (unsigned)n) atomicAdd(&g_deg[d], 1);
}

__global__ void scanA_kernel(int n) {
    __shared__ int s[512];
    int tid = threadIdx.x;
    int i = blockIdx.x * 512 + tid;
    s[tid] = (i < n) ? g_deg[i] : 0;
    __syncthreads();
    for (int off = 256; off > 0; off >>= 1) {
        if (tid < off) s[tid] += s[tid + off];
        __syncthreads();
    }
    if (tid == 0) g_part[blockIdx.x] = s[0];
}

__global__ void scanB_kernel(int nb) {
    __shared__ int s[512];
    int tid = threadIdx.x;
    int v = (tid < nb) ? g_part[tid] : 0;
    s[tid] = v;
    __syncthreads();
    for (int off = 1; off < 512; off <<= 1) {
        int tv = (tid >= off) ? s[tid - off] : 0;
        __syncthreads();
        s[tid] += tv;
        __syncthreads();
    }
    if (tid < nb) g_part[tid] = s[tid] - v;   // exclusive
}

__global__ void scanC_kernel(int n) {
    __shared__ int s[512];
    int tid = threadIdx.x;
    int i = blockIdx.x * 512 + tid;
    int v = (i < n) ? g_deg[i] : 0;
    s[tid] = v;
    __syncthreads();
    for (int off = 1; off < 512; off <<= 1) {
        int tv = (tid >= off) ? s[tid - off] : 0;
        __syncthreads();
        s[tid] += tv;
        __syncthreads();
    }
    if (i < n) {
        int start = g_part[blockIdx.x] + s[tid] - v;
        g_rowptr[i] = start;
        g_cursor[i] = start;
    }
}

__global__ void fill_kernel(const void* __restrict__ ei, int E, int n) {
    int e = blockIdx.x * blockDim.x + threadIdx.x;
    if (e >= E) return;
    int is64 = g_is64;
    int s = load_idx(ei, is64, (size_t)e);
    int d = load_idx(ei, is64, (size_t)E + e);
    if ((unsigned)d >= (unsigned)n || (unsigned)s >= (unsigned)n) return;
    int pos = atomicAdd(&g_cursor[d], 1);
    g_eidx[pos] = s;
}

// ---------------- fused gather: (BN+ReLU) + aggregate + hi/lo split ----------------
// BN==1: reads fp16 z from previous layer; computes its 2 BN coefficient columns
// inline from the stats slot (2 rsqrtf/thread — trivial).
template <int BN>
__global__ __launch_bounds__(256) void gather_kernel(const float* __restrict__ gamma,
                                                     const float* __restrict__ beta,
                                                     int slot, int n) {
    int gidx = blockIdx.x * blockDim.x + threadIdx.x;
    int wid = gidx >> 5;
    int node = wid >> 1;
    if (node >= n) return;
    int half = wid & 1;
    int lane = gidx & 31;
    int col = half * 64 + lane * 2;

    const __half* __restrict__ hsrc = BN ? (const __half*)g_zh : (const __half*)g_hx;

    float2 sc, sh;
    if (BN) {
        const float* st = g_stats + slot * 256;
        float invN = 1.f / (float)n;
        float m0 = st[col] * invN;
        float m1 = st[col + 1] * invN;
        float v0 = st[128 + col] * invN - m0 * m0;
        float v1 = st[128 + col + 1] * invN - m1 * m1;
        float r0 = rsqrtf(fmaxf(v0, 0.f) + 1e-5f);
        float r1 = rsqrtf(fmaxf(v1, 0.f) + 1e-5f);
        sc.x = gamma[col] * r0;     sc.y = gamma[col + 1] * r1;
        sh.x = beta[col] - m0 * sc.x;
        sh.y = beta[col + 1] - m1 * sc.y;
    }

    float2 v = __half22float2(*reinterpret_cast<const __half2*>(hsrc + (size_t)node * DIM + col));
    float ax, ay;
    if (BN) {
        ax = fmaxf(v.x * sc.x + sh.x, 0.f);
        ay = fmaxf(v.y * sc.y + sh.y, 0.f);
    } else {
        ax = v.x; ay = v.y;
    }

    int j = g_rowptr[node];
    int end = j + g_deg[node];
    for (; j + 4 <= end; j += 4) {
        int s0 = g_eidx[j], s1 = g_eidx[j + 1], s2 = g_eidx[j + 2], s3 = g_eidx[j + 3];
        float2 u0 = __half22float2(*reinterpret_cast<const __half2*>(hsrc + (size_t)s0 * DIM + col));
        float2 u1 = __half22float2(*reinterpret_cast<const __half2*>(hsrc + (size_t)s1 * DIM + col));
        float2 u2 = __half22float2(*reinterpret_cast<const __half2*>(hsrc + (size_t)s2 * DIM + col));
        float2 u3 = __half22float2(*reinterpret_cast<const __half2*>(hsrc + (size_t)s3 * DIM + col));
        if (BN) {
            ax += fmaxf(u0.x * sc.x + sh.x, 0.f) + fmaxf(u1.x * sc.x + sh.x, 0.f)
                + fmaxf(u2.x * sc.x + sh.x, 0.f) + fmaxf(u3.x * sc.x + sh.x, 0.f);
            ay += fmaxf(u0.y * sc.y + sh.y, 0.f) + fmaxf(u1.y * sc.y + sh.y, 0.f)
                + fmaxf(u2.y * sc.y + sh.y, 0.f) + fmaxf(u3.y * sc.y + sh.y, 0.f);
        } else {
            ax += u0.x + u1.x + u2.x + u3.x;
            ay += u0.y + u1.y + u2.y + u3.y;
        }
    }
    for (; j < end; j++) {
        int s = g_eidx[j];
        float2 u = __half22float2(*reinterpret_cast<const __half2*>(hsrc + (size_t)s * DIM + col));
        if (BN) {
            ax += fmaxf(u.x * sc.x + sh.x, 0.f);
            ay += fmaxf(u.y * sc.y + sh.y, 0.f);
        } else {
            ax += u.x; ay += u.y;
        }
    }

    __nv_bfloat16 h0 = __float2bfloat16(ax);
    __nv_bfloat16 h1 = __float2bfloat16(ay);
    __nv_bfloat16 l0 = __float2bfloat16(ax - __bfloat162float(h0));
    __nv_bfloat16 l1 = __float2bfloat16(ay - __bfloat162float(h1));
    union { __nv_bfloat162 b; uint32_t u; } HP, LP;
    HP.b.x = h0; HP.b.y = h1; LP.b.x = l0; LP.b.y = l1;
    __nv_bfloat16* op = g_as + (size_t)node * 256 + col;
    *reinterpret_cast<uint32_t*>(op) = HP.u;
    *reinterpret_cast<uint32_t*>(op + 128) = LP.u;
}

// ---------------- persistent fused MLP ----------------
#define ASTRIDE 264
#define WBYTES (128 * ASTRIDE * 2)
#define ABYTES (64 * ASTRIDE * 2)
#define SMEM_BYTES (2 * WBYTES + 2 * ABYTES)
#define MLP_GRID 148

__device__ __forceinline__ void mma_bf16(float d[4], const uint32_t a[4], const uint32_t b0, const uint32_t b1) {
    asm volatile(
        "mma.sync.aligned.m16n8k16.row.col.f32.bf16.bf16.f32 "
        "{%0,%1,%2,%3}, {%4,%5,%6,%7}, {%8,%9}, {%0,%1,%2,%3};\n"
        : "+f"(d[0]), "+f"(d[1]), "+f"(d[2]), "+f"(d[3])
        : "r"(a[0]), "r"(a[1]), "r"(a[2]), "r"(a[3]), "r"(b0), "r"(b1));
}

__device__ __forceinline__ void ldsm_x4(uint32_t r[4], uint32_t addr) {
    asm volatile("ldmatrix.sync.aligned.m8n8.x4.shared.b16 {%0,%1,%2,%3}, [%4];\n"
                 : "=r"(r[0]), "=r"(r[1]), "=r"(r[2]), "=r"(r[3]) : "r"(addr));
}

__device__ __forceinline__ void cpa16(uint32_t dst, const void* src) {
    asm volatile("cp.async.ca.shared.global [%0], [%1], 16;\n" :: "r"(dst), "l"(src));
}

// fused 3-pass k-loop; warp tile 16x32: 6 LDSM + 12 MMA per k-step
__device__ __forceinline__ void gemm_phase(uint32_t aAddr, const uint32_t bAddr0, const uint32_t bAddr1,
                                           float acc[4][4]) {
    uint32_t bA[2] = {bAddr0, bAddr1};
#pragma unroll
    for (int kk = 0; kk < 128; kk += 16) {
        uint32_t ah[4], al[4], bh[2][4], bl[2][4];
        ldsm_x4(ah, aAddr + kk * 2);
        ldsm_x4(al, aAddr + 256 + kk * 2);
#pragma unroll
        for (int np = 0; np < 2; np++) {
            ldsm_x4(bh[np], bA[np] + kk * 2);
            ldsm_x4(bl[np], bA[np] + 256 + kk * 2);
        }
#pragma unroll
        for (int nt = 0; nt < 4; nt++)
            mma_bf16(acc[nt], ah, bh[nt >> 1][(nt & 1) * 2], bh[nt >> 1][(nt & 1) * 2 + 1]);
#pragma unroll
        for (int nt = 0; nt < 4; nt++)
            mma_bf16(acc[nt], ah, bl[nt >> 1][(nt & 1) * 2], bl[nt >> 1][(nt & 1) * 2 + 1]);
#pragma unroll
        for (int nt = 0; nt < 4; nt++)
            mma_bf16(acc[nt], al, bh[nt >> 1][(nt & 1) * 2], bh[nt >> 1][(nt & 1) * 2 + 1]);
    }
}

__global__ __launch_bounds__(512, 1) void mlp_kernel(int layer, const float* __restrict__ b1,
                                                     const float* __restrict__ b2, int n) {
    extern __shared__ char smem_raw[];
    uint32_t sW1 = (uint32_t)__cvta_generic_to_shared(smem_raw);
    uint32_t sW2 = sW1 + WBYTES;
    uint32_t sA0 = sW2 + WBYTES;
    __shared__ float sb1[128], sb2[128], ssum[128], ssq[128];

    const __nv_bfloat16* __restrict__ W1g = g_wt + (size_t)(layer * 2 + 0) * 128 * 256;
    const __nv_bfloat16* __restrict__ W2g = g_wt + (size_t)(layer * 2 + 1) * 128 * 256;

    int tid = threadIdx.x;
    int numTiles = (n + 63) / 64;

    for (int i = tid; i < 4096; i += 512) {
        int r = i >> 5, s = i & 31;
        cpa16(sW1 + (r * ASTRIDE + s * 8) * 2, W1g + (size_t)r * 256 + s * 8);
        cpa16(sW2 + (r * ASTRIDE + s * 8) * 2, W2g + (size_t)r * 256 + s * 8);
    }
    {
        int tile = blockIdx.x;
        if (tile < numTiles) {
            int rb = tile * 64;
            for (int i = tid; i < 2048; i += 512) {
                int r = i >> 5, s = i & 31;
                int row = rb + r; if (row >= n) row = 0;
                cpa16(sA0 + (r * ASTRIDE + s * 8) * 2, g_as + (size_t)row * 256 + s * 8);
            }
        }
    }
    asm volatile("cp.async.commit_group;\n");
    if (tid < 128) { sb1[tid] = b1[tid]; sb2[tid] = b2[tid]; ssum[tid] = 0.f; ssq[tid] = 0.f; }

    int warp = tid >> 5, lane = tid & 31;
    int wm = warp & 3, wn = warp >> 2;          // 4(M) x 4(N) warp grid
    int mBase = wm * 16, nBase = wn * 32;       // warp tile 16 x 32
    int g = lane >> 2, t = lane & 3;
    int barid = 1 + wm;

    uint32_t aOff = (uint32_t)(((mBase + (lane & 15)) * ASTRIDE + (lane >> 4) * 8) * 2);
    uint32_t bOff0, bOff1;
    {
        int q = lane >> 3, rw = lane & 7;
        int rowoff = (q >> 1) * 8 + rw, coloff = (q & 1) * 8;
        bOff0 = (uint32_t)(((nBase + 0 + rowoff) * ASTRIDE + coloff) * 2);
        bOff1 = (uint32_t)(((nBase + 16 + rowoff) * ASTRIDE + coloff) * 2);
    }

    float cs[4][2], cq[4][2];
#pragma unroll
    for (int nt = 0; nt < 4; nt++) { cs[nt][0] = cs[nt][1] = 0.f; cq[nt][0] = cq[nt][1] = 0.f; }

    int buf = 0;
    for (int tile = blockIdx.x; tile < numTiles; tile += MLP_GRID) {
        asm volatile("cp.async.wait_group 0;\n" ::: "memory");
        __syncthreads();
        uint32_t sA = sA0 + buf * ABYTES;

        int next = tile + MLP_GRID;
        if (next < numTiles) {
            int rb = next * 64;
            uint32_t dstA = sA0 + (buf ^ 1) * ABYTES;
            for (int i = tid; i < 2048; i += 512) {
                int r = i >> 5, s = i & 31;
                int row = rb + r; if (row >= n) row = 0;
                cpa16(dstA + (r * ASTRIDE + s * 8) * 2, g_as + (size_t)row * 256 + s * 8);
            }
        }
        asm volatile("cp.async.commit_group;\n");

        // ---- GEMM 1 ----
        float acc[4][4];
#pragma unroll
        for (int b = 0; b < 4; b++)
#pragma unroll
            for (int c = 0; c < 4; c++) acc[b][c] = 0.f;
        gemm_phase(sA + aOff, sW1 + bOff0, sW1 + bOff1, acc);
        asm volatile("bar.sync %0, 128;" :: "r"(barid) : "memory");

        // epi 0: bias1 + relu + hi/lo split -> A[buf] rows of this group
#pragma unroll
        for (int i = 0; i < 2; i++) {
            int lrow = mBase + g + i * 8;
#pragma unroll
            for (int nt = 0; nt < 4; nt++) {
                int col = nBase + nt * 8 + t * 2;
                float v0 = fmaxf(acc[nt][i * 2 + 0] + sb1[col], 0.f);
                float v1 = fmaxf(acc[nt][i * 2 + 1] + sb1[col + 1], 0.f);
                __nv_bfloat16 h0 = __float2bfloat16(v0);
                __nv_bfloat16 h1 = __float2bfloat16(v1);
                __nv_bfloat16 l0 = __float2bfloat16(v0 - __bfloat162float(h0));
                __nv_bfloat16 l1 = __float2bfloat16(v1 - __bfloat162float(h1));
                union { __nv_bfloat162 b; uint32_t u; } HP, LP;
                HP.b.x = h0; HP.b.y = h1; LP.b.x = l0; LP.b.y = l1;
                uint32_t op = sA + (uint32_t)((lrow * ASTRIDE + col) * 2);
                asm volatile("st.shared.b32 [%0], %1;" :: "r"(op), "r"(HP.u));
                asm volatile("st.shared.b32 [%0], %1;" :: "r"(op + 256), "r"(LP.u));
            }
        }
        asm volatile("bar.sync %0, 128;" :: "r"(barid) : "memory");

        // ---- GEMM 2 ----
#pragma unroll
        for (int b = 0; b < 4; b++)
#pragma unroll
            for (int c = 0; c < 4; c++) acc[b][c] = 0.f;
        gemm_phase(sA + aOff, sW2 + bOff0, sW2 + bOff1, acc);

        // epi 1: bias2 -> g_zh (fp16) + register stats (fp32, unrounded)
        int rowBase = tile * 64;
#pragma unroll
        for (int i = 0; i < 2; i++) {
            int row = rowBase + mBase + g + i * 8;
            if (row >= n) continue;
#pragma unroll
            for (int nt = 0; nt < 4; nt++) {
                int col = nBase + nt * 8 + t * 2;
                float v0 = acc[nt][i * 2 + 0] + sb2[col];
                float v1 = acc[nt][i * 2 + 1] + sb2[col + 1];
                *reinterpret_cast<__half2*>(g_zh + (size_t)row * DIM + col) = __floats2half2_rn(v0, v1);
                cs[nt][0] += v0; cq[nt][0] += v0 * v0;
                cs[nt][1] += v1; cq[nt][1] += v1 * v1;
            }
        }
        buf ^= 1;
    }

    // final stats reduction: regs -> smem -> global slot (once per CTA)
    __syncthreads();
#pragma unroll
    for (int nt = 0; nt < 4; nt++) {
#pragma unroll
        for (int j = 0; j < 2; j++) {
            int col = nBase + nt * 8 + t * 2 + j;
            atomicAdd(&ssum[col], cs[nt][j]);
            atomicAdd(&ssq[col], cq[nt][j]);
        }
    }
    __syncthreads();
    if (tid < 128) {
        float* dst = g_stats + layer * 256;
        atomicAdd(&dst[tid], ssum[tid]);
        atomicAdd(&dst[128 + tid], ssq[tid]);
    }
}

// ---------------- final BN+ReLU -> d_out (reads fp16 z, inline BN coefficients) ----
__global__ void bnfinal_kernel(const float* __restrict__ gamma, const float* __restrict__ beta,
                               float* __restrict__ dout, int n) {
    int idx = blockIdx.x * blockDim.x + threadIdx.x;
    if (idx >= n * 32) return;
    int row = idx >> 5;
    int c4 = (idx & 31) * 4;
    const float* st = g_stats + 2 * 256;
    float invN = 1.f / (float)n;
    const __half2* zp = reinterpret_cast<const __half2*>(g_zh + (size_t)row * DIM + c4);
    float2 z01 = __half22float2(zp[0]);
    float2 z23 = __half22float2(zp[1]);
    float zz[4] = {z01.x, z01.y, z23.x, z23.y};
    float out[4];
#pragma unroll
    for (int j = 0; j < 4; j++) {
        int c = c4 + j;
        float mean = st[c] * invN;
        float var = st[128 + c] * invN - mean * mean;
        float rstd = rsqrtf(fmaxf(var, 0.f) + 1e-5f);
        out[j] = fmaxf(gamma[c] * (zz[j] - mean) * rstd + beta[c], 0.f);
    }
    float4 o; o.x = out[0]; o.y = out[1]; o.z = out[2]; o.w = out[3];
    *reinterpret_cast<float4*>(dout + (size_t)row * DIM + c4) = o;
}

// ---------------- host launcher ----------------
extern "C" void kernel_launch(void* const* d_in, const int* in_sizes, int n_in,
                              void* d_out, int out_size) {
    const float* x = (const float*)d_in[0];
    const void* ei = d_in[1];
    const float* W1 = (const float*)d_in[2];
    const float* b1 = (const float*)d_in[3];
    const float* W2 = (const float*)d_in[4];
    const float* b2 = (const float*)d_in[5];
    const float* gamma = (const float*)d_in[6];
    const float* beta = (const float*)d_in[7];
    (void)n_in; (void)out_size;

    int n = in_sizes[0] / DIM;
    int E = in_sizes[1] / 2;
    if (n > NNODES) n = NNODES;
    if (E > NEDGES) E = NEDGES;

    cudaFuncSetAttribute(mlp_kernel, cudaFuncAttributeMaxDynamicSharedMemorySize, SMEM_BYTES);

    int gatherBlocks = (n * 64 + 255) / 256;   // 2 warps per node
    int ewBlocks = (n * 32 + 255) / 256;

    detect_kernel<<<1, 256>>>(ei, E, n);
    wprep_kernel<<<(3 * 2 * 128 * 128 + 255) / 256, 256>>>(W1, W2);
    prepx_kernel<<<ewBlocks, 256>>>(x, n);
    hist_kernel<<<(E + 255) / 256, 256>>>(ei, E, n);
    int nsb = (n + 511) / 512;
    scanA_kernel<<<nsb, 512>>>(n);
    scanB_kernel<<<1, 512>>>(nsb);
    scanC_kernel<<<nsb, 512>>>(n);
    fill_kernel<<<(E + 255) / 256, 256>>>(ei, E, n);

    for (int l = 0; l < 3; l++) {
        if (l == 0) gather_kernel<0><<<gatherBlocks, 256>>>(nullptr, nullptr, 0, n);
        else gather_kernel<1><<<gatherBlocks, 256>>>(gamma + (l - 1) * 128, beta + (l - 1) * 128, l - 1, n);
        mlp_kernel<<<MLP_GRID, 512, SMEM_BYTES>>>(l, b1 + l * 128, b2 + l * 128, n);
    }
    bnfinal_kernel<<<ewBlocks, 256>>>(gamma + 2 * 128, beta + 2 * 128, (float*)d_out, n);
}

// round 14
// speedup vs baseline: 1.0695x; 1.0551x over previous
#include <cuda_runtime.h>
#include <cuda_bf16.h>
#include <cuda_fp16.h>
#include <cstdint>

#define NNODES 100000
#define NEDGES 800000
#define DIM 128

// ---------------- static scratch ----------------
__device__ __align__(16) __half g_zh[(size_t)NNODES * DIM];             // z staged fp16
__device__ __align__(16) __half g_hx[(size_t)NNODES * DIM];             // x staged fp16
__device__ __align__(16) __nv_bfloat16 g_as[(size_t)NNODES * 2 * DIM];  // [N][256] hi|lo
__device__ __align__(16) __nv_bfloat16 g_wt[6 * 128 * 256];             // [l*2+m][n][256] hi|lo
__device__ float g_stats[256];      // colsum|colsumsq; zeroed by finalize each layer
__device__ float g_bnScale[128];
__device__ float g_bnShift[128];
__device__ int g_deg[NNODES];
__device__ int g_rowptr[NNODES];
__device__ int g_cursor[NNODES];
__device__ int g_eidx[NEDGES];
__device__ int g_part[512];
__device__ int g_is64;

__device__ __forceinline__ int load_idx(const void* ei, int is64, size_t pos) {
    if (is64) return (int)((const long long*)ei)[pos];
    return ((const int*)ei)[pos];
}

// ---------------- weight prep + edge-dtype detection (block 0) ----------------
__global__ void wprep_kernel(const float* __restrict__ W1, const float* __restrict__ W2,
                             const void* __restrict__ ei, int E, int n) {
    if (blockIdx.x == 0) {
        // jax x64 trap: int32 data read as int64 packs next index into high word
        __shared__ int bad;
        if (threadIdx.x == 0) bad = 0;
        __syncthreads();
        const long long* p = (const long long*)ei;
        int m = (E < 4096) ? E : 4096;
        for (int i = threadIdx.x; i < m; i += blockDim.x) {
            long long v = p[i];
            if (v < 0 || v >= (long long)n) bad = 1;
        }
        __syncthreads();
        if (threadIdx.x == 0) g_is64 = bad ? 0 : 1;
    }
    int idx = blockIdx.x * blockDim.x + threadIdx.x;
    if (idx >= 3 * 2 * 128 * 128) return;
    int nn = idx & 127;
    int k = (idx >> 7) & 127;
    int m2 = (idx >> 14) & 1;
    int l = idx >> 15;
    const float* W = m2 ? W2 : W1;
    float v = W[((size_t)l * 128 + k) * 128 + nn];
    __nv_bfloat16 hi = __float2bfloat16(v);
    __nv_bfloat16 lo = __float2bfloat16(v - __bfloat162float(hi));
    size_t base = ((size_t)(l * 2 + m2) * 128 + nn) * 256;
    g_wt[base + k] = hi;
    g_wt[base + 128 + k] = lo;
}

// ---------------- x -> fp16 staging; zero degree counters ----------------
__global__ void prepx_kernel(const float* __restrict__ x, int n) {
    int idx = blockIdx.x * blockDim.x + threadIdx.x;
    if (idx < n) g_deg[idx] = 0;
    if (idx >= n * 32) return;
    int row = idx >> 5;
    int c4 = (idx & 31) * 4;
    float4 v = *reinterpret_cast<const float4*>(x + (size_t)row * DIM + c4);
    __half2 a = __floats2half2_rn(v.x, v.y);
    __half2 b = __floats2half2_rn(v.z, v.w);
    *reinterpret_cast<__half2*>(g_hx + (size_t)row * DIM + c4) = a;
    *reinterpret_cast<__half2*>(g_hx + (size_t)row * DIM + c4 + 2) = b;
}

// ---------------- CSR build ----------------
__global__ void hist_kernel(const void* __restrict__ ei, int E, int n) {
    int e = blockIdx.x * blockDim.x + threadIdx.x;
    if (e >= E) return;
    int d = load_idx(ei, g_is64, (size_t)E + e);
    if ((unsigned)d < (unsigned)n) atomicAdd(&g_deg[d], 1);
}

__global__ void scanA_kernel(int n) {
    __shared__ int s[512];
    int tid = threadIdx.x;
    int i = blockIdx.x * 512 + tid;
    s[tid] = (i < n) ? g_deg[i] : 0;
    __syncthreads();
    for (int off = 256; off > 0; off >>= 1) {
        if (tid < off) s[tid] += s[tid + off];
        __syncthreads();
    }
    if (tid == 0) g_part[blockIdx.x] = s[0];
}

__global__ void scanB_kernel(int nb) {
    __shared__ int s[512];
    int tid = threadIdx.x;
    int v = (tid < nb) ? g_part[tid] : 0;
    s[tid] = v;
    __syncthreads();
    for (int off = 1; off < 512; off <<= 1) {
        int tv = (tid >= off) ? s[tid - off] : 0;
        __syncthreads();
        s[tid] += tv;
        __syncthreads();
    }
    if (tid < nb) g_part[tid] = s[tid] - v;   // exclusive
}

__global__ void scanC_kernel(int n) {
    __shared__ int s[512];
    int tid = threadIdx.x;
    int i = blockIdx.x * 512 + tid;
    int v = (i < n) ? g_deg[i] : 0;
    s[tid] = v;
    __syncthreads();
    for (int off = 1; off < 512; off <<= 1) {
        int tv = (tid >= off) ? s[tid - off] : 0;
        __syncthreads();
        s[tid] += tv;
        __syncthreads();
    }
    if (i < n) {
        int start = g_part[blockIdx.x] + s[tid] - v;
        g_rowptr[i] = start;
        g_cursor[i] = start;
    }
}

__global__ void fill_kernel(const void* __restrict__ ei, int E, int n) {
    int e = blockIdx.x * blockDim.x + threadIdx.x;
    if (e >= E) return;
    int is64 = g_is64;
    int s = load_idx(ei, is64, (size_t)e);
    int d = load_idx(ei, is64, (size_t)E + e);
    if ((unsigned)d >= (unsigned)n || (unsigned)s >= (unsigned)n) return;
    int pos = atomicAdd(&g_cursor[d], 1);
    g_eidx[pos] = s;
}

// ---------------- fused gather: (BN+ReLU) + aggregate + hi/lo split ----------------
// 2 warps/node, fp16 rows, 8-edge unroll (8 independent loads in flight).
template <int BN>
__global__ __launch_bounds__(256) void gather_kernel(int n) {
    int gidx = blockIdx.x * blockDim.x + threadIdx.x;
    int wid = gidx >> 5;
    int node = wid >> 1;
    if (node >= n) return;
    int half = wid & 1;
    int lane = gidx & 31;
    int col = half * 64 + lane * 2;

    const __half* __restrict__ hsrc = BN ? (const __half*)g_zh : (const __half*)g_hx;

    float2 sc, sh;
    if (BN) {
        sc = *reinterpret_cast<const float2*>(g_bnScale + col);
        sh = *reinterpret_cast<const float2*>(g_bnShift + col);
    }

    float2 v = __half22float2(*reinterpret_cast<const __half2*>(hsrc + (size_t)node * DIM + col));
    float ax, ay;
    if (BN) {
        ax = fmaxf(v.x * sc.x + sh.x, 0.f);
        ay = fmaxf(v.y * sc.y + sh.y, 0.f);
    } else {
        ax = v.x; ay = v.y;
    }

    int j = g_rowptr[node];
    int end = j + g_deg[node];
    // 8-edge unroll
    for (; j + 8 <= end; j += 8) {
        float2 u[8];
#pragma unroll
        for (int q = 0; q < 8; q++) {
            int s = g_eidx[j + q];
            u[q] = __half22float2(*reinterpret_cast<const __half2*>(hsrc + (size_t)s * DIM + col));
        }
        if (BN) {
#pragma unroll
            for (int q = 0; q < 8; q++) {
                u[q].x = fmaxf(u[q].x * sc.x + sh.x, 0.f);
                u[q].y = fmaxf(u[q].y * sc.y + sh.y, 0.f);
            }
        }
        float x01 = u[0].x + u[1].x, x23 = u[2].x + u[3].x;
        float x45 = u[4].x + u[5].x, x67 = u[6].x + u[7].x;
        float y01 = u[0].y + u[1].y, y23 = u[2].y + u[3].y;
        float y45 = u[4].y + u[5].y, y67 = u[6].y + u[7].y;
        ax += (x01 + x23) + (x45 + x67);
        ay += (y01 + y23) + (y45 + y67);
    }
    // 4-edge tail
    for (; j + 4 <= end; j += 4) {
        float2 u[4];
#pragma unroll
        for (int q = 0; q < 4; q++) {
            int s = g_eidx[j + q];
            u[q] = __half22float2(*reinterpret_cast<const __half2*>(hsrc + (size_t)s * DIM + col));
        }
        if (BN) {
#pragma unroll
            for (int q = 0; q < 4; q++) {
                u[q].x = fmaxf(u[q].x * sc.x + sh.x, 0.f);
                u[q].y = fmaxf(u[q].y * sc.y + sh.y, 0.f);
            }
        }
        ax += (u[0].x + u[1].x) + (u[2].x + u[3].x);
        ay += (u[0].y + u[1].y) + (u[2].y + u[3].y);
    }
    for (; j < end; j++) {
        int s = g_eidx[j];
        float2 u = __half22float2(*reinterpret_cast<const __half2*>(hsrc + (size_t)s * DIM + col));
        if (BN) {
            ax += fmaxf(u.x * sc.x + sh.x, 0.f);
            ay += fmaxf(u.y * sc.y + sh.y, 0.f);
        } else {
            ax += u.x; ay += u.y;
        }
    }

    __nv_bfloat16 h0 = __float2bfloat16(ax);
    __nv_bfloat16 h1 = __float2bfloat16(ay);
    __nv_bfloat16 l0 = __float2bfloat16(ax - __bfloat162float(h0));
    __nv_bfloat16 l1 = __float2bfloat16(ay - __bfloat162float(h1));
    union { __nv_bfloat162 b; uint32_t u; } HP, LP;
    HP.b.x = h0; HP.b.y = h1; LP.b.x = l0; LP.b.y = l1;
    __nv_bfloat16* op = g_as + (size_t)node * 256 + col;
    *reinterpret_cast<uint32_t*>(op) = HP.u;
    *reinterpret_cast<uint32_t*>(op + 128) = LP.u;
}

// ---------------- persistent fused MLP ----------------
#define ASTRIDE 264
#define WBYTES (128 * ASTRIDE * 2)
#define ABYTES (64 * ASTRIDE * 2)
#define SMEM_BYTES (2 * WBYTES + 2 * ABYTES)
#define MLP_GRID 148

__device__ __forceinline__ void mma_bf16(float d[4], const uint32_t a[4], const uint32_t b0, const uint32_t b1) {
    asm volatile(
        "mma.sync.aligned.m16n8k16.row.col.f32.bf16.bf16.f32 "
        "{%0,%1,%2,%3}, {%4,%5,%6,%7}, {%8,%9}, {%0,%1,%2,%3};\n"
        : "+f"(d[0]), "+f"(d[1]), "+f"(d[2]), "+f"(d[3])
        : "r"(a[0]), "r"(a[1]), "r"(a[2]), "r"(a[3]), "r"(b0), "r"(b1));
}

__device__ __forceinline__ void ldsm_x4(uint32_t r[4], uint32_t addr) {
    asm volatile("ldmatrix.sync.aligned.m8n8.x4.shared.b16 {%0,%1,%2,%3}, [%4];\n"
                 : "=r"(r[0]), "=r"(r[1]), "=r"(r[2]), "=r"(r[3]) : "r"(addr));
}

__device__ __forceinline__ void cpa16(uint32_t dst, const void* src) {
    asm volatile("cp.async.ca.shared.global [%0], [%1], 16;\n" :: "r"(dst), "l"(src));
}

// fused 3-pass k-loop; warp tile 16x32: 6 LDSM + 12 MMA per k-step
__device__ __forceinline__ void gemm_phase(uint32_t aAddr, const uint32_t bAddr0, const uint32_t bAddr1,
                                           float acc[4][4]) {
    uint32_t bA[2] = {bAddr0, bAddr1};
#pragma unroll
    for (int kk = 0; kk < 128; kk += 16) {
        uint32_t ah[4], al[4], bh[2][4], bl[2][4];
        ldsm_x4(ah, aAddr + kk * 2);
        ldsm_x4(al, aAddr + 256 + kk * 2);
#pragma unroll
        for (int np = 0; np < 2; np++) {
            ldsm_x4(bh[np], bA[np] + kk * 2);
            ldsm_x4(bl[np], bA[np] + 256 + kk * 2);
        }
#pragma unroll
        for (int nt = 0; nt < 4; nt++)
            mma_bf16(acc[nt], ah, bh[nt >> 1][(nt & 1) * 2], bh[nt >> 1][(nt & 1) * 2 + 1]);
#pragma unroll
        for (int nt = 0; nt < 4; nt++)
            mma_bf16(acc[nt], ah, bl[nt >> 1][(nt & 1) * 2], bl[nt >> 1][(nt & 1) * 2 + 1]);
#pragma unroll
        for (int nt = 0; nt < 4; nt++)
            mma_bf16(acc[nt], al, bh[nt >> 1][(nt & 1) * 2], bh[nt >> 1][(nt & 1) * 2 + 1]);
    }
}

__global__ __launch_bounds__(512, 1) void mlp_kernel(int layer, const float* __restrict__ b1,
                                                     const float* __restrict__ b2, int n) {
    extern __shared__ char smem_raw[];
    uint32_t sW1 = (uint32_t)__cvta_generic_to_shared(smem_raw);
    uint32_t sW2 = sW1 + WBYTES;
    uint32_t sA0 = sW2 + WBYTES;
    __shared__ float sb1[128], sb2[128], ssum[128], ssq[128];

    const __nv_bfloat16* __restrict__ W1g = g_wt + (size_t)(layer * 2 + 0) * 128 * 256;
    const __nv_bfloat16* __restrict__ W2g = g_wt + (size_t)(layer * 2 + 1) * 128 * 256;

    int tid = threadIdx.x;
    int numTiles = (n + 63) / 64;

    for (int i = tid; i < 4096; i += 512) {
        int r = i >> 5, s = i & 31;
        cpa16(sW1 + (r * ASTRIDE + s * 8) * 2, W1g + (size_t)r * 256 + s * 8);
        cpa16(sW2 + (r * ASTRIDE + s * 8) * 2, W2g + (size_t)r * 256 + s * 8);
    }
    {
        int tile = blockIdx.x;
        if (tile < numTiles) {
            int rb = tile * 64;
            for (int i = tid; i < 2048; i += 512) {
                int r = i >> 5, s = i & 31;
                int row = rb + r; if (row >= n) row = 0;
                cpa16(sA0 + (r * ASTRIDE + s * 8) * 2, g_as + (size_t)row * 256 + s * 8);
            }
        }
    }
    asm volatile("cp.async.commit_group;\n");
    if (tid < 128) { sb1[tid] = b1[tid]; sb2[tid] = b2[tid]; ssum[tid] = 0.f; ssq[tid] = 0.f; }

    int warp = tid >> 5, lane = tid & 31;
    int wm = warp & 3, wn = warp >> 2;          // 4(M) x 4(N) warp grid
    int mBase = wm * 16, nBase = wn * 32;       // warp tile 16 x 32
    int g = lane >> 2, t = lane & 3;
    int barid = 1 + wm;

    uint32_t aOff = (uint32_t)(((mBase + (lane & 15)) * ASTRIDE + (lane >> 4) * 8) * 2);
    uint32_t bOff0, bOff1;
    {
        int q = lane >> 3, rw = lane & 7;
        int rowoff = (q >> 1) * 8 + rw, coloff = (q & 1) * 8;
        bOff0 = (uint32_t)(((nBase + 0 + rowoff) * ASTRIDE + coloff) * 2);
        bOff1 = (uint32_t)(((nBase + 16 + rowoff) * ASTRIDE + coloff) * 2);
    }

    float cs[4][2], cq[4][2];
#pragma unroll
    for (int nt = 0; nt < 4; nt++) { cs[nt][0] = cs[nt][1] = 0.f; cq[nt][0] = cq[nt][1] = 0.f; }

    int buf = 0;
    for (int tile = blockIdx.x; tile < numTiles; tile += MLP_GRID) {
        asm volatile("cp.async.wait_group 0;\n" ::: "memory");
        __syncthreads();
        uint32_t sA = sA0 + buf * ABYTES;

        int next = tile + MLP_GRID;
        if (next < numTiles) {
            int rb = next * 64;
            uint32_t dstA = sA0 + (buf ^ 1) * ABYTES;
            for (int i = tid; i < 2048; i += 512) {
                int r = i >> 5, s = i & 31;
                int row = rb + r; if (row >= n) row = 0;
                cpa16(dstA + (r * ASTRIDE + s * 8) * 2, g_as + (size_t)row * 256 + s * 8);
            }
        }
        asm volatile("cp.async.commit_group;\n");

        // ---- GEMM 1 ----
        float acc[4][4];
#pragma unroll
        for (int b = 0; b < 4; b++)
#pragma unroll
            for (int c = 0; c < 4; c++) acc[b][c] = 0.f;
        gemm_phase(sA + aOff, sW1 + bOff0, sW1 + bOff1, acc);
        asm volatile("bar.sync %0, 128;" :: "r"(barid) : "memory");

        // epi 0: bias1 + relu + hi/lo split -> A[buf] rows of this group
#pragma unroll
        for (int i = 0; i < 2; i++) {
            int lrow = mBase + g + i * 8;
#pragma unroll
            for (int nt = 0; nt < 4; nt++) {
                int col = nBase + nt * 8 + t * 2;
                float v0 = fmaxf(acc[nt][i * 2 + 0] + sb1[col], 0.f);
                float v1 = fmaxf(acc[nt][i * 2 + 1] + sb1[col + 1], 0.f);
                __nv_bfloat16 h0 = __float2bfloat16(v0);
                __nv_bfloat16 h1 = __float2bfloat16(v1);
                __nv_bfloat16 l0 = __float2bfloat16(v0 - __bfloat162float(h0));
                __nv_bfloat16 l1 = __float2bfloat16(v1 - __bfloat162float(h1));
                union { __nv_bfloat162 b; uint32_t u; } HP, LP;
                HP.b.x = h0; HP.b.y = h1; LP.b.x = l0; LP.b.y = l1;
                uint32_t op = sA + (uint32_t)((lrow * ASTRIDE + col) * 2);
                asm volatile("st.shared.b32 [%0], %1;" :: "r"(op), "r"(HP.u));
                asm volatile("st.shared.b32 [%0], %1;" :: "r"(op + 256), "r"(LP.u));
            }
        }
        asm volatile("bar.sync %0, 128;" :: "r"(barid) : "memory");

        // ---- GEMM 2 ----
#pragma unroll
        for (int b = 0; b < 4; b++)
#pragma unroll
            for (int c = 0; c < 4; c++) acc[b][c] = 0.f;
        gemm_phase(sA + aOff, sW2 + bOff0, sW2 + bOff1, acc);

        // epi 1: bias2 -> g_zh (fp16) + register stats (fp32, unrounded)
        int rowBase = tile * 64;
#pragma unroll
        for (int i = 0; i < 2; i++) {
            int row = rowBase + mBase + g + i * 8;
            if (row >= n) continue;
#pragma unroll
            for (int nt = 0; nt < 4; nt++) {
                int col = nBase + nt * 8 + t * 2;
                float v0 = acc[nt][i * 2 + 0] + sb2[col];
                float v1 = acc[nt][i * 2 + 1] + sb2[col + 1];
                *reinterpret_cast<__half2*>(g_zh + (size_t)row * DIM + col) = __floats2half2_rn(v0, v1);
                cs[nt][0] += v0; cq[nt][0] += v0 * v0;
                cs[nt][1] += v1; cq[nt][1] += v1 * v1;
            }
        }
        buf ^= 1;
    }

    // final stats reduction: regs -> smem -> global (once per CTA)
    __syncthreads();
#pragma unroll
    for (int nt = 0; nt < 4; nt++) {
#pragma unroll
        for (int j = 0; j < 2; j++) {
            int col = nBase + nt * 8 + t * 2 + j;
            atomicAdd(&ssum[col], cs[nt][j]);
            atomicAdd(&ssq[col], cq[nt][j]);
        }
    }
    __syncthreads();
    if (tid < 128) {
        atomicAdd(&g_stats[tid], ssum[tid]);
        atomicAdd(&g_stats[128 + tid], ssq[tid]);
    }
}

// ---------------- stats finalize: scale/shift, then zero stats ----------------
__global__ void finalize_kernel(const float* __restrict__ gamma, const float* __restrict__ beta, int n) {
    int c = threadIdx.x;
    if (c < 128) {
        float invN = 1.f / (float)n;
        float mean = g_stats[c] * invN;
        float var = g_stats[128 + c] * invN - mean * mean;
        float rstd = rsqrtf(fmaxf(var, 0.f) + 1e-5f);
        float scale = gamma[c] * rstd;
        g_bnScale[c] = scale;
        g_bnShift[c] = beta[c] - mean * scale;
        g_stats[c] = 0.f;
        g_stats[128 + c] = 0.f;
    }
}

// ---------------- final BN+ReLU -> d_out (reads fp16 z, precomputed coefficients) ----
__global__ void bnfinal_kernel(float* __restrict__ dout, int n) {
    int idx = blockIdx.x * blockDim.x + threadIdx.x;
    if (idx >= n * 32) return;
    int row = idx >> 5;
    int c4 = (idx & 31) * 4;
    const __half2* zp = reinterpret_cast<const __half2*>(g_zh + (size_t)row * DIM + c4);
    float2 z01 = __half22float2(zp[0]);
    float2 z23 = __half22float2(zp[1]);
    float4 sc = *reinterpret_cast<const float4*>(g_bnScale + c4);
    float4 sh = *reinterpret_cast<const float4*>(g_bnShift + c4);
    float4 o;
    o.x = fmaxf(z01.x * sc.x + sh.x, 0.f);
    o.y = fmaxf(z01.y * sc.y + sh.y, 0.f);
    o.z = fmaxf(z23.x * sc.z + sh.z, 0.f);
    o.w = fmaxf(z23.y * sc.w + sh.w, 0.f);
    *reinterpret_cast<float4*>(dout + (size_t)row * DIM + c4) = o;
}

// ---------------- host launcher ----------------
extern "C" void kernel_launch(void* const* d_in, const int* in_sizes, int n_in,
                              void* d_out, int out_size) {
    const float* x = (const float*)d_in[0];
    const void* ei = d_in[1];
    const float* W1 = (const float*)d_in[2];
    const float* b1 = (const float*)d_in[3];
    const float* W2 = (const float*)d_in[4];
    const float* b2 = (const float*)d_in[5];
    const float* gamma = (const float*)d_in[6];
    const float* beta = (const float*)d_in[7];
    (void)n_in; (void)out_size;

    int n = in_sizes[0] / DIM;
    int E = in_sizes[1] / 2;
    if (n > NNODES) n = NNODES;
    if (E > NEDGES) E = NEDGES;

    cudaFuncSetAttribute(mlp_kernel, cudaFuncAttributeMaxDynamicSharedMemorySize, SMEM_BYTES);

    int gatherBlocks = (n * 64 + 255) / 256;   // 2 warps per node
    int ewBlocks = (n * 32 + 255) / 256;

    wprep_kernel<<<(3 * 2 * 128 * 128 + 255) / 256, 256>>>(W1, W2, ei, E, n);
    prepx_kernel<<<ewBlocks, 256>>>(x, n);
    hist_kernel<<<(E + 255) / 256, 256>>>(ei, E, n);
    int nsb = (n + 511) / 512;
    scanA_kernel<<<nsb, 512>>>(n);
    scanB_kernel<<<1, 512>>>(nsb);
    scanC_kernel<<<nsb, 512>>>(n);
    fill_kernel<<<(E + 255) / 256, 256>>>(ei, E, n);

    for (int l = 0; l < 3; l++) {
        if (l == 0) gather_kernel<0><<<gatherBlocks, 256>>>(n);
        else gather_kernel<1><<<gatherBlocks, 256>>>(n);
        mlp_kernel<<<MLP_GRID, 512, SMEM_BYTES>>>(l, b1 + l * 128, b2 + l * 128, n);
        finalize_kernel<<<1, 128>>>(gamma + l * 128, beta + l * 128, n);
    }
    bnfinal_kernel<<<ewBlocks, 256>>>((float*)d_out, n);
}

// round 15
// speedup vs baseline: 1.0893x; 1.0185x over previous
#include <cuda_runtime.h>
#include <cuda_bf16.h>
#include <cuda_fp16.h>
#include <cstdint>

#define NNODES 100000
#define NEDGES 800000
#define DIM 128

// ---------------- static scratch ----------------
__device__ __align__(16) __half g_zh[(size_t)NNODES * DIM];             // z staged fp16
__device__ __align__(16) __half g_hx[(size_t)NNODES * DIM];             // x staged fp16
__device__ __align__(16) __nv_bfloat16 g_as[(size_t)NNODES * 2 * DIM];  // [N][256] hi|lo
__device__ __align__(16) __nv_bfloat16 g_wt[6 * 128 * 256];             // [l*2+m][n][256] hi|lo
__device__ float g_stats[256];      // colsum|colsumsq; zeroed by finalize each layer
__device__ float g_bnScale[128];
__device__ float g_bnShift[128];
__device__ int g_deg[NNODES];
__device__ int g_rowptr[NNODES];
__device__ int g_cursor[NNODES];
__device__ int g_eidx[NEDGES];
__device__ int g_part[512];
__device__ int g_is64;

__device__ __forceinline__ int load_idx(const void* ei, int is64, size_t pos) {
    if (is64) return (int)((const long long*)ei)[pos];
    return ((const int*)ei)[pos];
}

// ---------------- weight prep + edge-dtype detection (block 0) ----------------
__global__ void wprep_kernel(const float* __restrict__ W1, const float* __restrict__ W2,
                             const void* __restrict__ ei, int E, int n) {
    if (blockIdx.x == 0) {
        __shared__ int bad;
        if (threadIdx.x == 0) bad = 0;
        __syncthreads();
        const long long* p = (const long long*)ei;
        int m = (E < 4096) ? E : 4096;
        for (int i = threadIdx.x; i < m; i += blockDim.x) {
            long long v = p[i];
            if (v < 0 || v >= (long long)n) bad = 1;
        }
        __syncthreads();
        if (threadIdx.x == 0) g_is64 = bad ? 0 : 1;
    }
    int idx = blockIdx.x * blockDim.x + threadIdx.x;
    if (idx >= 3 * 2 * 128 * 128) return;
    int nn = idx & 127;
    int k = (idx >> 7) & 127;
    int m2 = (idx >> 14) & 1;
    int l = idx >> 15;
    const float* W = m2 ? W2 : W1;
    float v = W[((size_t)l * 128 + k) * 128 + nn];
    __nv_bfloat16 hi = __float2bfloat16(v);
    __nv_bfloat16 lo = __float2bfloat16(v - __bfloat162float(hi));
    size_t base = ((size_t)(l * 2 + m2) * 128 + nn) * 256;
    g_wt[base + k] = hi;
    g_wt[base + 128 + k] = lo;
}

// ---------------- x -> fp16 staging; zero degree counters ----------------
__global__ void prepx_kernel(const float* __restrict__ x, int n) {
    int idx = blockIdx.x * blockDim.x + threadIdx.x;
    if (idx < n) g_deg[idx] = 0;
    if (idx >= n * 32) return;
    int row = idx >> 5;
    int c4 = (idx & 31) * 4;
    float4 v = *reinterpret_cast<const float4*>(x + (size_t)row * DIM + c4);
    __half2 a = __floats2half2_rn(v.x, v.y);
    __half2 b = __floats2half2_rn(v.z, v.w);
    *reinterpret_cast<__half2*>(g_hx + (size_t)row * DIM + c4) = a;
    *reinterpret_cast<__half2*>(g_hx + (size_t)row * DIM + c4 + 2) = b;
}

// ---------------- CSR build ----------------
__global__ void hist_kernel(const void* __restrict__ ei, int E, int n) {
    int e = blockIdx.x * blockDim.x + threadIdx.x;
    if (e >= E) return;
    int d = load_idx(ei, g_is64, (size_t)E + e);
    if ((unsigned)d < (unsigned)n) atomicAdd(&g_deg[d], 1);
}

__global__ void scanA_kernel(int n) {
    __shared__ int s[512];
    int tid = threadIdx.x;
    int i = blockIdx.x * 512 + tid;
    s[tid] = (i < n) ? g_deg[i] : 0;
    __syncthreads();
    for (int off = 256; off > 0; off >>= 1) {
        if (tid < off) s[tid] += s[tid + off];
        __syncthreads();
    }
    if (tid == 0) g_part[blockIdx.x] = s[0];
}

__global__ void scanB_kernel(int nb) {
    __shared__ int s[512];
    int tid = threadIdx.x;
    int v = (tid < nb) ? g_part[tid] : 0;
    s[tid] = v;
    __syncthreads();
    for (int off = 1; off < 512; off <<= 1) {
        int tv = (tid >= off) ? s[tid - off] : 0;
        __syncthreads();
        s[tid] += tv;
        __syncthreads();
    }
    if (tid < nb) g_part[tid] = s[tid] - v;   // exclusive
}

__global__ void scanC_kernel(int n) {
    __shared__ int s[512];
    int tid = threadIdx.x;
    int i = blockIdx.x * 512 + tid;
    int v = (i < n) ? g_deg[i] : 0;
    s[tid] = v;
    __syncthreads();
    for (int off = 1; off < 512; off <<= 1) {
        int tv = (tid >= off) ? s[tid - off] : 0;
        __syncthreads();
        s[tid] += tv;
        __syncthreads();
    }
    if (i < n) {
        int start = g_part[blockIdx.x] + s[tid] - v;
        g_rowptr[i] = start;
        g_cursor[i] = start;
    }
}

__global__ void fill_kernel(const void* __restrict__ ei, int E, int n) {
    int e = blockIdx.x * blockDim.x + threadIdx.x;
    if (e >= E) return;
    int is64 = g_is64;
    int s = load_idx(ei, is64, (size_t)e);
    int d = load_idx(ei, is64, (size_t)E + e);
    if ((unsigned)d >= (unsigned)n || (unsigned)s >= (unsigned)n) return;
    int pos = atomicAdd(&g_cursor[d], 1);
    g_eidx[pos] = s;
}

// ---------------- fused gather: (BN+ReLU) + aggregate + hi/lo split ----------------
template <int BN>
__global__ __launch_bounds__(256) void gather_kernel(int n) {
    int gidx = blockIdx.x * blockDim.x + threadIdx.x;
    int wid = gidx >> 5;
    int node = wid >> 1;
    if (node >= n) return;
    int half = wid & 1;
    int lane = gidx & 31;
    int col = half * 64 + lane * 2;

    const __half* __restrict__ hsrc = BN ? (const __half*)g_zh : (const __half*)g_hx;

    float2 sc, sh;
    if (BN) {
        sc = *reinterpret_cast<const float2*>(g_bnScale + col);
        sh = *reinterpret_cast<const float2*>(g_bnShift + col);
    }

    float2 v = __half22float2(*reinterpret_cast<const __half2*>(hsrc + (size_t)node * DIM + col));
    float ax, ay;
    if (BN) {
        ax = fmaxf(v.x * sc.x + sh.x, 0.f);
        ay = fmaxf(v.y * sc.y + sh.y, 0.f);
    } else {
        ax = v.x; ay = v.y;
    }

    int j = g_rowptr[node];
    int end = j + g_deg[node];
    for (; j + 8 <= end; j += 8) {
        float2 u[8];
#pragma unroll
        for (int q = 0; q < 8; q++) {
            int s = g_eidx[j + q];
            u[q] = __half22float2(*reinterpret_cast<const __half2*>(hsrc + (size_t)s * DIM + col));
        }
        if (BN) {
#pragma unroll
            for (int q = 0; q < 8; q++) {
                u[q].x = fmaxf(u[q].x * sc.x + sh.x, 0.f);
                u[q].y = fmaxf(u[q].y * sc.y + sh.y, 0.f);
            }
        }
        float x01 = u[0].x + u[1].x, x23 = u[2].x + u[3].x;
        float x45 = u[4].x + u[5].x, x67 = u[6].x + u[7].x;
        float y01 = u[0].y + u[1].y, y23 = u[2].y + u[3].y;
        float y45 = u[4].y + u[5].y, y67 = u[6].y + u[7].y;
        ax += (x01 + x23) + (x45 + x67);
        ay += (y01 + y23) + (y45 + y67);
    }
    for (; j + 4 <= end; j += 4) {
        float2 u[4];
#pragma unroll
        for (int q = 0; q < 4; q++) {
            int s = g_eidx[j + q];
            u[q] = __half22float2(*reinterpret_cast<const __half2*>(hsrc + (size_t)s * DIM + col));
        }
        if (BN) {
#pragma unroll
            for (int q = 0; q < 4; q++) {
                u[q].x = fmaxf(u[q].x * sc.x + sh.x, 0.f);
                u[q].y = fmaxf(u[q].y * sc.y + sh.y, 0.f);
            }
        }
        ax += (u[0].x + u[1].x) + (u[2].x + u[3].x);
        ay += (u[0].y + u[1].y) + (u[2].y + u[3].y);
    }
    for (; j < end; j++) {
        int s = g_eidx[j];
        float2 u = __half22float2(*reinterpret_cast<const __half2*>(hsrc + (size_t)s * DIM + col));
        if (BN) {
            ax += fmaxf(u.x * sc.x + sh.x, 0.f);
            ay += fmaxf(u.y * sc.y + sh.y, 0.f);
        } else {
            ax += u.x; ay += u.y;
        }
    }

    __nv_bfloat16 h0 = __float2bfloat16(ax);
    __nv_bfloat16 h1 = __float2bfloat16(ay);
    __nv_bfloat16 l0 = __float2bfloat16(ax - __bfloat162float(h0));
    __nv_bfloat16 l1 = __float2bfloat16(ay - __bfloat162float(h1));
    union { __nv_bfloat162 b; uint32_t u; } HP, LP;
    HP.b.x = h0; HP.b.y = h1; LP.b.x = l0; LP.b.y = l1;
    __nv_bfloat16* op = g_as + (size_t)node * 256 + col;
    *reinterpret_cast<uint32_t*>(op) = HP.u;
    *reinterpret_cast<uint32_t*>(op + 128) = LP.u;
}

// ---------------- persistent fused MLP — 4 decoupled row-group pipelines ----------------
// All A-buffer traffic inside the tile loop is row-group-local (rows [16*wm,16*wm+16)):
// gemm_phase reads them (aOff), epi-0 writes them, and now each group PREFETCHES its
// own rows of the next tile. The loop therefore needs only group-local named barriers;
// the 4 groups run as independent pipelines, hiding each other's stalls.
#define ASTRIDE 264
#define WBYTES (128 * ASTRIDE * 2)
#define ABYTES (64 * ASTRIDE * 2)
#define SMEM_BYTES (2 * WBYTES + 2 * ABYTES)
#define MLP_GRID 148

__device__ __forceinline__ void mma_bf16(float d[4], const uint32_t a[4], const uint32_t b0, const uint32_t b1) {
    asm volatile(
        "mma.sync.aligned.m16n8k16.row.col.f32.bf16.bf16.f32 "
        "{%0,%1,%2,%3}, {%4,%5,%6,%7}, {%8,%9}, {%0,%1,%2,%3};\n"
        : "+f"(d[0]), "+f"(d[1]), "+f"(d[2]), "+f"(d[3])
        : "r"(a[0]), "r"(a[1]), "r"(a[2]), "r"(a[3]), "r"(b0), "r"(b1));
}

__device__ __forceinline__ void ldsm_x4(uint32_t r[4], uint32_t addr) {
    asm volatile("ldmatrix.sync.aligned.m8n8.x4.shared.b16 {%0,%1,%2,%3}, [%4];\n"
                 : "=r"(r[0]), "=r"(r[1]), "=r"(r[2]), "=r"(r[3]) : "r"(addr));
}

__device__ __forceinline__ void cpa16(uint32_t dst, const void* src) {
    asm volatile("cp.async.ca.shared.global [%0], [%1], 16;\n" :: "r"(dst), "l"(src));
}

// fused 3-pass k-loop; warp tile 16x32: 6 LDSM + 12 MMA per k-step
__device__ __forceinline__ void gemm_phase(uint32_t aAddr, const uint32_t bAddr0, const uint32_t bAddr1,
                                           float acc[4][4]) {
    uint32_t bA[2] = {bAddr0, bAddr1};
#pragma unroll
    for (int kk = 0; kk < 128; kk += 16) {
        uint32_t ah[4], al[4], bh[2][4], bl[2][4];
        ldsm_x4(ah, aAddr + kk * 2);
        ldsm_x4(al, aAddr + 256 + kk * 2);
#pragma unroll
        for (int np = 0; np < 2; np++) {
            ldsm_x4(bh[np], bA[np] + kk * 2);
            ldsm_x4(bl[np], bA[np] + 256 + kk * 2);
        }
#pragma unroll
        for (int nt = 0; nt < 4; nt++)
            mma_bf16(acc[nt], ah, bh[nt >> 1][(nt & 1) * 2], bh[nt >> 1][(nt & 1) * 2 + 1]);
#pragma unroll
        for (int nt = 0; nt < 4; nt++)
            mma_bf16(acc[nt], ah, bl[nt >> 1][(nt & 1) * 2], bl[nt >> 1][(nt & 1) * 2 + 1]);
#pragma unroll
        for (int nt = 0; nt < 4; nt++)
            mma_bf16(acc[nt], al, bh[nt >> 1][(nt & 1) * 2], bh[nt >> 1][(nt & 1) * 2 + 1]);
    }
}

__global__ __launch_bounds__(512, 1) void mlp_kernel(int layer, const float* __restrict__ b1,
                                                     const float* __restrict__ b2, int n) {
    extern __shared__ char smem_raw[];
    uint32_t sW1 = (uint32_t)__cvta_generic_to_shared(smem_raw);
    uint32_t sW2 = sW1 + WBYTES;
    uint32_t sA0 = sW2 + WBYTES;
    __shared__ float sb1[128], sb2[128], ssum[128], ssq[128];

    const __nv_bfloat16* __restrict__ W1g = g_wt + (size_t)(layer * 2 + 0) * 128 * 256;
    const __nv_bfloat16* __restrict__ W2g = g_wt + (size_t)(layer * 2 + 1) * 128 * 256;

    int tid = threadIdx.x;
    int numTiles = (n + 63) / 64;

    int warp = tid >> 5, lane = tid & 31;
    int wm = warp & 3, wn = warp >> 2;          // 4(M) x 4(N) warp grid
    int mBase = wm * 16, nBase = wn * 32;       // warp tile 16 x 32
    int g = lane >> 2, t = lane & 3;
    int barid = 1 + wm;
    int gtid = (wn << 5) | lane;                // 0..127 within row-group

    // resident weights (all threads)
    for (int i = tid; i < 4096; i += 512) {
        int r = i >> 5, s = i & 31;
        cpa16(sW1 + (r * ASTRIDE + s * 8) * 2, W1g + (size_t)r * 256 + s * 8);
        cpa16(sW2 + (r * ASTRIDE + s * 8) * 2, W2g + (size_t)r * 256 + s * 8);
    }
    // first A tile: each group loads its own 16 rows
    {
        int tile = blockIdx.x;
        if (tile < numTiles) {
            int rb = tile * 64;
            for (int i = gtid; i < 512; i += 128) {
                int r = mBase + (i >> 5);
                int s = i & 31;
                int row = rb + r; if (row >= n) row = 0;
                cpa16(sA0 + (r * ASTRIDE + s * 8) * 2, g_as + (size_t)row * 256 + s * 8);
            }
        }
    }
    asm volatile("cp.async.commit_group;\n");
    if (tid < 128) { sb1[tid] = b1[tid]; sb2[tid] = b2[tid]; ssum[tid] = 0.f; ssq[tid] = 0.f; }
    asm volatile("cp.async.wait_group 0;\n" ::: "memory");
    __syncthreads();   // once: W + first A + biases visible to all

    uint32_t aOff = (uint32_t)(((mBase + (lane & 15)) * ASTRIDE + (lane >> 4) * 8) * 2);
    uint32_t bOff0, bOff1;
    {
        int q = lane >> 3, rw = lane & 7;
        int rowoff = (q >> 1) * 8 + rw, coloff = (q & 1) * 8;
        bOff0 = (uint32_t)(((nBase + 0 + rowoff) * ASTRIDE + coloff) * 2);
        bOff1 = (uint32_t)(((nBase + 16 + rowoff) * ASTRIDE + coloff) * 2);
    }

    float cs[4][2], cq[4][2];
#pragma unroll
    for (int nt = 0; nt < 4; nt++) { cs[nt][0] = cs[nt][1] = 0.f; cq[nt][0] = cq[nt][1] = 0.f; }

    int buf = 0;
    for (int tile = blockIdx.x; tile < numTiles; tile += MLP_GRID) {
        uint32_t sA = sA0 + buf * ABYTES;

        // group-local prefetch of next tile's rows into buf^1
        int next = tile + MLP_GRID;
        if (next < numTiles) {
            int rb = next * 64;
            uint32_t dstA = sA0 + (buf ^ 1) * ABYTES;
            for (int i = gtid; i < 512; i += 128) {
                int r = mBase + (i >> 5);
                int s = i & 31;
                int row = rb + r; if (row >= n) row = 0;
                cpa16(dstA + (r * ASTRIDE + s * 8) * 2, g_as + (size_t)row * 256 + s * 8);
            }
        }
        asm volatile("cp.async.commit_group;\n");

        // ---- GEMM 1 ----
        float acc[4][4];
#pragma unroll
        for (int b = 0; b < 4; b++)
#pragma unroll
            for (int c = 0; c < 4; c++) acc[b][c] = 0.f;
        gemm_phase(sA + aOff, sW1 + bOff0, sW1 + bOff1, acc);
        asm volatile("bar.sync %0, 128;" :: "r"(barid) : "memory");

        // epi 0: bias1 + relu + hi/lo split -> this group's rows of buf
#pragma unroll
        for (int i = 0; i < 2; i++) {
            int lrow = mBase + g + i * 8;
#pragma unroll
            for (int nt = 0; nt < 4; nt++) {
                int col = nBase + nt * 8 + t * 2;
                float v0 = fmaxf(acc[nt][i * 2 + 0] + sb1[col], 0.f);
                float v1 = fmaxf(acc[nt][i * 2 + 1] + sb1[col + 1], 0.f);
                __nv_bfloat16 h0 = __float2bfloat16(v0);
                __nv_bfloat16 h1 = __float2bfloat16(v1);
                __nv_bfloat16 l0 = __float2bfloat16(v0 - __bfloat162float(h0));
                __nv_bfloat16 l1 = __float2bfloat16(v1 - __bfloat162float(h1));
                union { __nv_bfloat162 b; uint32_t u; } HP, LP;
                HP.b.x = h0; HP.b.y = h1; LP.b.x = l0; LP.b.y = l1;
                uint32_t op = sA + (uint32_t)((lrow * ASTRIDE + col) * 2);
                asm volatile("st.shared.b32 [%0], %1;" :: "r"(op), "r"(HP.u));
                asm volatile("st.shared.b32 [%0], %1;" :: "r"(op + 256), "r"(LP.u));
            }
        }
        asm volatile("bar.sync %0, 128;" :: "r"(barid) : "memory");

        // ---- GEMM 2 ----
#pragma unroll
        for (int b = 0; b < 4; b++)
#pragma unroll
            for (int c = 0; c < 4; c++) acc[b][c] = 0.f;
        gemm_phase(sA + aOff, sW2 + bOff0, sW2 + bOff1, acc);

        // epi 1: bias2 -> g_zh (fp16) + register stats (fp32, unrounded)
        int rowBase = tile * 64;
#pragma unroll
        for (int i = 0; i < 2; i++) {
            int row = rowBase + mBase + g + i * 8;
            if (row >= n) continue;
#pragma unroll
            for (int nt = 0; nt < 4; nt++) {
                int col = nBase + nt * 8 + t * 2;
                float v0 = acc[nt][i * 2 + 0] + sb2[col];
                float v1 = acc[nt][i * 2 + 1] + sb2[col + 1];
                *reinterpret_cast<__half2*>(g_zh + (size_t)row * DIM + col) = __floats2half2_rn(v0, v1);
                cs[nt][0] += v0; cq[nt][0] += v0 * v0;
                cs[nt][1] += v1; cq[nt][1] += v1 * v1;
            }
        }

        // wait for this group's prefetch, then group barrier before reading buf^1
        asm volatile("cp.async.wait_group 0;\n" ::: "memory");
        asm volatile("bar.sync %0, 128;" :: "r"(barid) : "memory");
        buf ^= 1;
    }

    // final stats reduction: regs -> smem -> global (once per CTA)
    __syncthreads();
#pragma unroll
    for (int nt = 0; nt < 4; nt++) {
#pragma unroll
        for (int j = 0; j < 2; j++) {
            int col = nBase + nt * 8 + t * 2 + j;
            atomicAdd(&ssum[col], cs[nt][j]);
            atomicAdd(&ssq[col], cq[nt][j]);
        }
    }
    __syncthreads();
    if (tid < 128) {
        atomicAdd(&g_stats[tid], ssum[tid]);
        atomicAdd(&g_stats[128 + tid], ssq[tid]);
    }
}

// ---------------- stats finalize: scale/shift, then zero stats ----------------
__global__ void finalize_kernel(const float* __restrict__ gamma, const float* __restrict__ beta, int n) {
    int c = threadIdx.x;
    if (c < 128) {
        float invN = 1.f / (float)n;
        float mean = g_stats[c] * invN;
        float var = g_stats[128 + c] * invN - mean * mean;
        float rstd = rsqrtf(fmaxf(var, 0.f) + 1e-5f);
        float scale = gamma[c] * rstd;
        g_bnScale[c] = scale;
        g_bnShift[c] = beta[c] - mean * scale;
        g_stats[c] = 0.f;
        g_stats[128 + c] = 0.f;
    }
}

// ---------------- final BN+ReLU -> d_out ----------------
__global__ void bnfinal_kernel(float* __restrict__ dout, int n) {
    int idx = blockIdx.x * blockDim.x + threadIdx.x;
    if (idx >= n * 32) return;
    int row = idx >> 5;
    int c4 = (idx & 31) * 4;
    const __half2* zp = reinterpret_cast<const __half2*>(g_zh + (size_t)row * DIM + c4);
    float2 z01 = __half22float2(zp[0]);
    float2 z23 = __half22float2(zp[1]);
    float4 sc = *reinterpret_cast<const float4*>(g_bnScale + c4);
    float4 sh = *reinterpret_cast<const float4*>(g_bnShift + c4);
    float4 o;
    o.x = fmaxf(z01.x * sc.x + sh.x, 0.f);
    o.y = fmaxf(z01.y * sc.y + sh.y, 0.f);
    o.z = fmaxf(z23.x * sc.z + sh.z, 0.f);
    o.w = fmaxf(z23.y * sc.w + sh.w, 0.f);
    *reinterpret_cast<float4*>(dout + (size_t)row * DIM + c4) = o;
}

// ---------------- host launcher ----------------
extern "C" void kernel_launch(void* const* d_in, const int* in_sizes, int n_in,
                              void* d_out, int out_size) {
    const float* x = (const float*)d_in[0];
    const void* ei = d_in[1];
    const float* W1 = (const float*)d_in[2];
    const float* b1 = (const float*)d_in[3];
    const float* W2 = (const float*)d_in[4];
    const float* b2 = (const float*)d_in[5];
    const float* gamma = (const float*)d_in[6];
    const float* beta = (const float*)d_in[7];
    (void)n_in; (void)out_size;

    int n = in_sizes[0] / DIM;
    int E = in_sizes[1] / 2;
    if (n > NNODES) n = NNODES;
    if (E > NEDGES) E = NEDGES;

    cudaFuncSetAttribute(mlp_kernel, cudaFuncAttributeMaxDynamicSharedMemorySize, SMEM_BYTES);

    int gatherBlocks = (n * 64 + 255) / 256;   // 2 warps per node
    int ewBlocks = (n * 32 + 255) / 256;

    wprep_kernel<<<(3 * 2 * 128 * 128 + 255) / 256, 256>>>(W1, W2, ei, E, n);
    prepx_kernel<<<ewBlocks, 256>>>(x, n);
    hist_kernel<<<(E + 255) / 256, 256>>>(ei, E, n);
    int nsb = (n + 511) / 512;
    scanA_kernel<<<nsb, 512>>>(n);
    scanB_kernel<<<1, 512>>>(nsb);
    scanC_kernel<<<nsb, 512>>>(n);
    fill_kernel<<<(E + 255) / 256, 256>>>(ei, E, n);

    for (int l = 0; l < 3; l++) {
        if (l == 0) gather_kernel<0><<<gatherBlocks, 256>>>(n);
        else gather_kernel<1><<<gatherBlocks, 256>>>(n);
        mlp_kernel<<<MLP_GRID, 512, SMEM_BYTES>>>(l, b1 + l * 128, b2 + l * 128, n);
        finalize_kernel<<<1, 128>>>(gamma + l * 128, beta + l * 128, n);
    }
    bnfinal_kernel<<<ewBlocks, 256>>>((float*)d_out, n);
}

// round 16
// speedup vs baseline: 1.0940x; 1.0043x over previous
#include <cuda_runtime.h>
#include <cuda_bf16.h>
#include <cuda_fp16.h>
#include <cstdint>

#define NNODES 100000
#define NEDGES 800000
#define DIM 128

// ---------------- static scratch ----------------
__device__ __align__(16) __half g_zh[(size_t)NNODES * DIM];             // z staged fp16
__device__ __align__(16) __half g_hx[(size_t)NNODES * DIM];             // x staged fp16
__device__ __align__(16) __nv_bfloat16 g_as[(size_t)NNODES * 2 * DIM];  // [N][256] hi|lo
__device__ __align__(16) __nv_bfloat16 g_wt[6 * 128 * 256];             // [l*2+m][n][256] hi|lo
__device__ float g_stats[256];      // colsum|colsumsq; zeroed by last mlp CTA each layer
__device__ float g_bnScale[128];
__device__ float g_bnShift[128];
__device__ int g_mlpDone;           // last-CTA election counter (reset each layer)
__device__ int g_deg[NNODES];
__device__ int g_rowptr[NNODES];
__device__ int g_cursor[NNODES];
__device__ int g_eidx[NEDGES];
__device__ int g_part[512];
__device__ int g_is64;

__device__ __forceinline__ int load_idx(const void* ei, int is64, size_t pos) {
    if (is64) return (int)((const long long*)ei)[pos];
    return ((const int*)ei)[pos];
}

// ---------------- weight prep + edge-dtype detection (block 0) ----------------
__global__ void wprep_kernel(const float* __restrict__ W1, const float* __restrict__ W2,
                             const void* __restrict__ ei, int E, int n) {
    if (blockIdx.x == 0) {
        __shared__ int bad;
        if (threadIdx.x == 0) bad = 0;
        __syncthreads();
        const long long* p = (const long long*)ei;
        int m = (E < 4096) ? E : 4096;
        for (int i = threadIdx.x; i < m; i += blockDim.x) {
            long long v = p[i];
            if (v < 0 || v >= (long long)n) bad = 1;
        }
        __syncthreads();
        if (threadIdx.x == 0) g_is64 = bad ? 0 : 1;
    }
    int idx = blockIdx.x * blockDim.x + threadIdx.x;
    if (idx >= 3 * 2 * 128 * 128) return;
    int nn = idx & 127;
    int k = (idx >> 7) & 127;
    int m2 = (idx >> 14) & 1;
    int l = idx >> 15;
    const float* W = m2 ? W2 : W1;
    float v = W[((size_t)l * 128 + k) * 128 + nn];
    __nv_bfloat16 hi = __float2bfloat16(v);
    __nv_bfloat16 lo = __float2bfloat16(v - __bfloat162float(hi));
    size_t base = ((size_t)(l * 2 + m2) * 128 + nn) * 256;
    g_wt[base + k] = hi;
    g_wt[base + 128 + k] = lo;
}

// ---------------- x -> fp16 staging; zero degree counters ----------------
__global__ void prepx_kernel(const float* __restrict__ x, int n) {
    int idx = blockIdx.x * blockDim.x + threadIdx.x;
    if (idx < n) g_deg[idx] = 0;
    if (idx >= n * 32) return;
    int row = idx >> 5;
    int c4 = (idx & 31) * 4;
    float4 v = *reinterpret_cast<const float4*>(x + (size_t)row * DIM + c4);
    __half2 a = __floats2half2_rn(v.x, v.y);
    __half2 b = __floats2half2_rn(v.z, v.w);
    *reinterpret_cast<__half2*>(g_hx + (size_t)row * DIM + c4) = a;
    *reinterpret_cast<__half2*>(g_hx + (size_t)row * DIM + c4 + 2) = b;
}

// ---------------- CSR build ----------------
__global__ void hist_kernel(const void* __restrict__ ei, int E, int n) {
    int e = blockIdx.x * blockDim.x + threadIdx.x;
    if (e >= E) return;
    int d = load_idx(ei, g_is64, (size_t)E + e);
    if ((unsigned)d < (unsigned)n) atomicAdd(&g_deg[d], 1);
}

__global__ void scanA_kernel(int n) {
    __shared__ int s[512];
    int tid = threadIdx.x;
    int i = blockIdx.x * 512 + tid;
    s[tid] = (i < n) ? g_deg[i] : 0;
    __syncthreads();
    for (int off = 256; off > 0; off >>= 1) {
        if (tid < off) s[tid] += s[tid + off];
        __syncthreads();
    }
    if (tid == 0) g_part[blockIdx.x] = s[0];
}

__global__ void scanB_kernel(int nb) {
    __shared__ int s[512];
    int tid = threadIdx.x;
    int v = (tid < nb) ? g_part[tid] : 0;
    s[tid] = v;
    __syncthreads();
    for (int off = 1; off < 512; off <<= 1) {
        int tv = (tid >= off) ? s[tid - off] : 0;
        __syncthreads();
        s[tid] += tv;
        __syncthreads();
    }
    if (tid < nb) g_part[tid] = s[tid] - v;   // exclusive
}

__global__ void scanC_kernel(int n) {
    __shared__ int s[512];
    int tid = threadIdx.x;
    int i = blockIdx.x * 512 + tid;
    int v = (i < n) ? g_deg[i] : 0;
    s[tid] = v;
    __syncthreads();
    for (int off = 1; off < 512; off <<= 1) {
        int tv = (tid >= off) ? s[tid - off] : 0;
        __syncthreads();
        s[tid] += tv;
        __syncthreads();
    }
    if (i < n) {
        int start = g_part[blockIdx.x] + s[tid] - v;
        g_rowptr[i] = start;
        g_cursor[i] = start;
    }
}

__global__ void fill_kernel(const void* __restrict__ ei, int E, int n) {
    int e = blockIdx.x * blockDim.x + threadIdx.x;
    if (e >= E) return;
    int is64 = g_is64;
    int s = load_idx(ei, is64, (size_t)e);
    int d = load_idx(ei, is64, (size_t)E + e);
    if ((unsigned)d >= (unsigned)n || (unsigned)s >= (unsigned)n) return;
    int pos = atomicAdd(&g_cursor[d], 1);
    g_eidx[pos] = s;
}

// ---------------- fused gather: (BN+ReLU) + aggregate + hi/lo split ----------------
template <int BN>
__global__ __launch_bounds__(256) void gather_kernel(int n) {
    int gidx = blockIdx.x * blockDim.x + threadIdx.x;
    int wid = gidx >> 5;
    int node = wid >> 1;
    if (node >= n) return;
    int half = wid & 1;
    int lane = gidx & 31;
    int col = half * 64 + lane * 2;

    const __half* __restrict__ hsrc = BN ? (const __half*)g_zh : (const __half*)g_hx;

    float2 sc, sh;
    if (BN) {
        sc = *reinterpret_cast<const float2*>(g_bnScale + col);
        sh = *reinterpret_cast<const float2*>(g_bnShift + col);
    }

    float2 v = __half22float2(*reinterpret_cast<const __half2*>(hsrc + (size_t)node * DIM + col));
    float ax, ay;
    if (BN) {
        ax = fmaxf(v.x * sc.x + sh.x, 0.f);
        ay = fmaxf(v.y * sc.y + sh.y, 0.f);
    } else {
        ax = v.x; ay = v.y;
    }

    int j = g_rowptr[node];
    int end = j + g_deg[node];
    for (; j + 8 <= end; j += 8) {
        float2 u[8];
#pragma unroll
        for (int q = 0; q < 8; q++) {
            int s = g_eidx[j + q];
            u[q] = __half22float2(*reinterpret_cast<const __half2*>(hsrc + (size_t)s * DIM + col));
        }
        if (BN) {
#pragma unroll
            for (int q = 0; q < 8; q++) {
                u[q].x = fmaxf(u[q].x * sc.x + sh.x, 0.f);
                u[q].y = fmaxf(u[q].y * sc.y + sh.y, 0.f);
            }
        }
        float x01 = u[0].x + u[1].x, x23 = u[2].x + u[3].x;
        float x45 = u[4].x + u[5].x, x67 = u[6].x + u[7].x;
        float y01 = u[0].y + u[1].y, y23 = u[2].y + u[3].y;
        float y45 = u[4].y + u[5].y, y67 = u[6].y + u[7].y;
        ax += (x01 + x23) + (x45 + x67);
        ay += (y01 + y23) + (y45 + y67);
    }
    for (; j + 4 <= end; j += 4) {
        float2 u[4];
#pragma unroll
        for (int q = 0; q < 4; q++) {
            int s = g_eidx[j + q];
            u[q] = __half22float2(*reinterpret_cast<const __half2*>(hsrc + (size_t)s * DIM + col));
        }
        if (BN) {
#pragma unroll
            for (int q = 0; q < 4; q++) {
                u[q].x = fmaxf(u[q].x * sc.x + sh.x, 0.f);
                u[q].y = fmaxf(u[q].y * sc.y + sh.y, 0.f);
            }
        }
        ax += (u[0].x + u[1].x) + (u[2].x + u[3].x);
        ay += (u[0].y + u[1].y) + (u[2].y + u[3].y);
    }
    for (; j < end; j++) {
        int s = g_eidx[j];
        float2 u = __half22float2(*reinterpret_cast<const __half2*>(hsrc + (size_t)s * DIM + col));
        if (BN) {
            ax += fmaxf(u.x * sc.x + sh.x, 0.f);
            ay += fmaxf(u.y * sc.y + sh.y, 0.f);
        } else {
            ax += u.x; ay += u.y;
        }
    }

    __nv_bfloat16 h0 = __float2bfloat16(ax);
    __nv_bfloat16 h1 = __float2bfloat16(ay);
    __nv_bfloat16 l0 = __float2bfloat16(ax - __bfloat162float(h0));
    __nv_bfloat16 l1 = __float2bfloat16(ay - __bfloat162float(h1));
    union { __nv_bfloat162 b; uint32_t u; } HP, LP;
    HP.b.x = h0; HP.b.y = h1; LP.b.x = l0; LP.b.y = l1;
    __nv_bfloat16* op = g_as + (size_t)node * 256 + col;
    *reinterpret_cast<uint32_t*>(op) = HP.u;
    *reinterpret_cast<uint32_t*>(op + 128) = LP.u;
}

// ---------------- persistent fused MLP — 4 decoupled row-group pipelines ----------------
#define ASTRIDE 264
#define WBYTES (128 * ASTRIDE * 2)
#define ABYTES (64 * ASTRIDE * 2)
#define SMEM_BYTES (2 * WBYTES + 2 * ABYTES)
#define MLP_GRID 148

__device__ __forceinline__ void mma_bf16(float d[4], const uint32_t a[4], const uint32_t b0, const uint32_t b1) {
    asm volatile(
        "mma.sync.aligned.m16n8k16.row.col.f32.bf16.bf16.f32 "
        "{%0,%1,%2,%3}, {%4,%5,%6,%7}, {%8,%9}, {%0,%1,%2,%3};\n"
        : "+f"(d[0]), "+f"(d[1]), "+f"(d[2]), "+f"(d[3])
        : "r"(a[0]), "r"(a[1]), "r"(a[2]), "r"(a[3]), "r"(b0), "r"(b1));
}

__device__ __forceinline__ void ldsm_x4(uint32_t r[4], uint32_t addr) {
    asm volatile("ldmatrix.sync.aligned.m8n8.x4.shared.b16 {%0,%1,%2,%3}, [%4];\n"
                 : "=r"(r[0]), "=r"(r[1]), "=r"(r[2]), "=r"(r[3]) : "r"(addr));
}

__device__ __forceinline__ void cpa16(uint32_t dst, const void* src) {
    asm volatile("cp.async.ca.shared.global [%0], [%1], 16;\n" :: "r"(dst), "l"(src));
}

// fused 3-pass k-loop; warp tile 16x32: 6 LDSM + 12 MMA per k-step
__device__ __forceinline__ void gemm_phase(uint32_t aAddr, const uint32_t bAddr0, const uint32_t bAddr1,
                                           float acc[4][4]) {
    uint32_t bA[2] = {bAddr0, bAddr1};
#pragma unroll
    for (int kk = 0; kk < 128; kk += 16) {
        uint32_t ah[4], al[4], bh[2][4], bl[2][4];
        ldsm_x4(ah, aAddr + kk * 2);
        ldsm_x4(al, aAddr + 256 + kk * 2);
#pragma unroll
        for (int np = 0; np < 2; np++) {
            ldsm_x4(bh[np], bA[np] + kk * 2);
            ldsm_x4(bl[np], bA[np] + 256 + kk * 2);
        }
#pragma unroll
        for (int nt = 0; nt < 4; nt++)
            mma_bf16(acc[nt], ah, bh[nt >> 1][(nt & 1) * 2], bh[nt >> 1][(nt & 1) * 2 + 1]);
#pragma unroll
        for (int nt = 0; nt < 4; nt++)
            mma_bf16(acc[nt], ah, bl[nt >> 1][(nt & 1) * 2], bl[nt >> 1][(nt & 1) * 2 + 1]);
#pragma unroll
        for (int nt = 0; nt < 4; nt++)
            mma_bf16(acc[nt], al, bh[nt >> 1][(nt & 1) * 2], bh[nt >> 1][(nt & 1) * 2 + 1]);
    }
}

__global__ __launch_bounds__(512, 1) void mlp_kernel(int layer, const float* __restrict__ b1,
                                                     const float* __restrict__ b2,
                                                     const float* __restrict__ gamma,
                                                     const float* __restrict__ beta, int n) {
    extern __shared__ char smem_raw[];
    uint32_t sW1 = (uint32_t)__cvta_generic_to_shared(smem_raw);
    uint32_t sW2 = sW1 + WBYTES;
    uint32_t sA0 = sW2 + WBYTES;
    __shared__ float sb1[128], sb2[128], ssum[128], ssq[128];
    __shared__ int sLast;

    const __nv_bfloat16* __restrict__ W1g = g_wt + (size_t)(layer * 2 + 0) * 128 * 256;
    const __nv_bfloat16* __restrict__ W2g = g_wt + (size_t)(layer * 2 + 1) * 128 * 256;

    int tid = threadIdx.x;
    int numTiles = (n + 63) / 64;

    int warp = tid >> 5, lane = tid & 31;
    int wm = warp & 3, wn = warp >> 2;          // 4(M) x 4(N) warp grid
    int mBase = wm * 16, nBase = wn * 32;       // warp tile 16 x 32
    int g = lane >> 2, t = lane & 3;
    int barid = 1 + wm;
    int gtid = (wn << 5) | lane;                // 0..127 within row-group

    for (int i = tid; i < 4096; i += 512) {
        int r = i >> 5, s = i & 31;
        cpa16(sW1 + (r * ASTRIDE + s * 8) * 2, W1g + (size_t)r * 256 + s * 8);
        cpa16(sW2 + (r * ASTRIDE + s * 8) * 2, W2g + (size_t)r * 256 + s * 8);
    }
    {
        int tile = blockIdx.x;
        if (tile < numTiles) {
            int rb = tile * 64;
            for (int i = gtid; i < 512; i += 128) {
                int r = mBase + (i >> 5);
                int s = i & 31;
                int row = rb + r; if (row >= n) row = 0;
                cpa16(sA0 + (r * ASTRIDE + s * 8) * 2, g_as + (size_t)row * 256 + s * 8);
            }
        }
    }
    asm volatile("cp.async.commit_group;\n");
    if (tid < 128) { sb1[tid] = b1[tid]; sb2[tid] = b2[tid]; ssum[tid] = 0.f; ssq[tid] = 0.f; }
    asm volatile("cp.async.wait_group 0;\n" ::: "memory");
    __syncthreads();

    uint32_t aOff = (uint32_t)(((mBase + (lane & 15)) * ASTRIDE + (lane >> 4) * 8) * 2);
    uint32_t bOff0, bOff1;
    {
        int q = lane >> 3, rw = lane & 7;
        int rowoff = (q >> 1) * 8 + rw, coloff = (q & 1) * 8;
        bOff0 = (uint32_t)(((nBase + 0 + rowoff) * ASTRIDE + coloff) * 2);
        bOff1 = (uint32_t)(((nBase + 16 + rowoff) * ASTRIDE + coloff) * 2);
    }

    float cs[4][2], cq[4][2];
#pragma unroll
    for (int nt = 0; nt < 4; nt++) { cs[nt][0] = cs[nt][1] = 0.f; cq[nt][0] = cq[nt][1] = 0.f; }

    int buf = 0;
    for (int tile = blockIdx.x; tile < numTiles; tile += MLP_GRID) {
        uint32_t sA = sA0 + buf * ABYTES;

        int next = tile + MLP_GRID;
        if (next < numTiles) {
            int rb = next * 64;
            uint32_t dstA = sA0 + (buf ^ 1) * ABYTES;
            for (int i = gtid; i < 512; i += 128) {
                int r = mBase + (i >> 5);
                int s = i & 31;
                int row = rb + r; if (row >= n) row = 0;
                cpa16(dstA + (r * ASTRIDE + s * 8) * 2, g_as + (size_t)row * 256 + s * 8);
            }
        }
        asm volatile("cp.async.commit_group;\n");

        // ---- GEMM 1 ----
        float acc[4][4];
#pragma unroll
        for (int b = 0; b < 4; b++)
#pragma unroll
            for (int c = 0; c < 4; c++) acc[b][c] = 0.f;
        gemm_phase(sA + aOff, sW1 + bOff0, sW1 + bOff1, acc);
        asm volatile("bar.sync %0, 128;" :: "r"(barid) : "memory");

        // epi 0: bias1 + relu + hi/lo split -> this group's rows of buf
#pragma unroll
        for (int i = 0; i < 2; i++) {
            int lrow = mBase + g + i * 8;
#pragma unroll
            for (int nt = 0; nt < 4; nt++) {
                int col = nBase + nt * 8 + t * 2;
                float v0 = fmaxf(acc[nt][i * 2 + 0] + sb1[col], 0.f);
                float v1 = fmaxf(acc[nt][i * 2 + 1] + sb1[col + 1], 0.f);
                __nv_bfloat16 h0 = __float2bfloat16(v0);
                __nv_bfloat16 h1 = __float2bfloat16(v1);
                __nv_bfloat16 l0 = __float2bfloat16(v0 - __bfloat162float(h0));
                __nv_bfloat16 l1 = __float2bfloat16(v1 - __bfloat162float(h1));
                union { __nv_bfloat162 b; uint32_t u; } HP, LP;
                HP.b.x = h0; HP.b.y = h1; LP.b.x = l0; LP.b.y = l1;
                uint32_t op = sA + (uint32_t)((lrow * ASTRIDE + col) * 2);
                asm volatile("st.shared.b32 [%0], %1;" :: "r"(op), "r"(HP.u));
                asm volatile("st.shared.b32 [%0], %1;" :: "r"(op + 256), "r"(LP.u));
            }
        }
        asm volatile("bar.sync %0, 128;" :: "r"(barid) : "memory");

        // ---- GEMM 2 ----
#pragma unroll
        for (int b = 0; b < 4; b++)
#pragma unroll
            for (int c = 0; c < 4; c++) acc[b][c] = 0.f;
        gemm_phase(sA + aOff, sW2 + bOff0, sW2 + bOff1, acc);

        // epi 1: bias2 -> g_zh (fp16) + register stats (fp32, unrounded)
        int rowBase = tile * 64;
#pragma unroll
        for (int i = 0; i < 2; i++) {
            int row = rowBase + mBase + g + i * 8;
            if (row >= n) continue;
#pragma unroll
            for (int nt = 0; nt < 4; nt++) {
                int col = nBase + nt * 8 + t * 2;
                float v0 = acc[nt][i * 2 + 0] + sb2[col];
                float v1 = acc[nt][i * 2 + 1] + sb2[col + 1];
                *reinterpret_cast<__half2*>(g_zh + (size_t)row * DIM + col) = __floats2half2_rn(v0, v1);
                cs[nt][0] += v0; cq[nt][0] += v0 * v0;
                cs[nt][1] += v1; cq[nt][1] += v1 * v1;
            }
        }

        asm volatile("cp.async.wait_group 0;\n" ::: "memory");
        asm volatile("bar.sync %0, 128;" :: "r"(barid) : "memory");
        buf ^= 1;
    }

    // ---- stats reduction: regs -> smem -> global, then last-CTA BN finalize ----
    __syncthreads();
#pragma unroll
    for (int nt = 0; nt < 4; nt++) {
#pragma unroll
        for (int j = 0; j < 2; j++) {
            int col = nBase + nt * 8 + t * 2 + j;
            atomicAdd(&ssum[col], cs[nt][j]);
            atomicAdd(&ssq[col], cq[nt][j]);
        }
    }
    __syncthreads();
    if (tid < 128) {
        atomicAdd(&g_stats[tid], ssum[tid]);
        atomicAdd(&g_stats[128 + tid], ssq[tid]);
    }
    __threadfence();
    __syncthreads();
    if (tid == 0) {
        int prev = atomicAdd(&g_mlpDone, 1);
        sLast = (prev == MLP_GRID - 1) ? 1 : 0;
    }
    __syncthreads();
    if (sLast) {
        if (tid < 128) {
            int c = tid;
            float invN = 1.f / (float)n;
            float mean = g_stats[c] * invN;
            float var = g_stats[128 + c] * invN - mean * mean;
            float rstd = rsqrtf(fmaxf(var, 0.f) + 1e-5f);
            float scale = gamma[c] * rstd;
            g_bnScale[c] = scale;
            g_bnShift[c] = beta[c] - mean * scale;
            g_stats[c] = 0.f;
            g_stats[128 + c] = 0.f;
        }
        if (tid == 0) g_mlpDone = 0;
    }
}

// ---------------- final BN+ReLU -> d_out ----------------
__global__ void bnfinal_kernel(float* __restrict__ dout, int n) {
    int idx = blockIdx.x * blockDim.x + threadIdx.x;
    if (idx >= n * 32) return;
    int row = idx >> 5;
    int c4 = (idx & 31) * 4;
    const __half2* zp = reinterpret_cast<const __half2*>(g_zh + (size_t)row * DIM + c4);
    float2 z01 = __half22float2(zp[0]);
    float2 z23 = __half22float2(zp[1]);
    float4 sc = *reinterpret_cast<const float4*>(g_bnScale + c4);
    float4 sh = *reinterpret_cast<const float4*>(g_bnShift + c4);
    float4 o;
    o.x = fmaxf(z01.x * sc.x + sh.x, 0.f);
    o.y = fmaxf(z01.y * sc.y + sh.y, 0.f);
    o.z = fmaxf(z23.x * sc.z + sh.z, 0.f);
    o.w = fmaxf(z23.y * sc.w + sh.w, 0.f);
    *reinterpret_cast<float4*>(dout + (size_t)row * DIM + c4) = o;
}

// ---------------- host launcher ----------------
extern "C" void kernel_launch(void* const* d_in, const int* in_sizes, int n_in,
                              void* d_out, int out_size) {
    const float* x = (const float*)d_in[0];
    const void* ei = d_in[1];
    const float* W1 = (const float*)d_in[2];
    const float* b1 = (const float*)d_in[3];
    const float* W2 = (const float*)d_in[4];
    const float* b2 = (const float*)d_in[5];
    const float* gamma = (const float*)d_in[6];
    const float* beta = (const float*)d_in[7];
    (void)n_in; (void)out_size;

    int n = in_sizes[0] / DIM;
    int E = in_sizes[1] / 2;
    if (n > NNODES) n = NNODES;
    if (E > NEDGES) E = NEDGES;

    cudaFuncSetAttribute(mlp_kernel, cudaFuncAttributeMaxDynamicSharedMemorySize, SMEM_BYTES);

    int gatherBlocks = (n * 64 + 255) / 256;   // 2 warps per node
    int ewBlocks = (n * 32 + 255) / 256;

    wprep_kernel<<<(3 * 2 * 128 * 128 + 255) / 256, 256>>>(W1, W2, ei, E, n);
    prepx_kernel<<<ewBlocks, 256>>>(x, n);
    hist_kernel<<<(E + 255) / 256, 256>>>(ei, E, n);
    int nsb = (n + 511) / 512;
    scanA_kernel<<<nsb, 512>>>(n);
    scanB_kernel<<<1, 512>>>(nsb);
    scanC_kernel<<<nsb, 512>>>(n);
    fill_kernel<<<(E + 255) / 256, 256>>>(ei, E, n);

    for (int l = 0; l < 3; l++) {
        if (l == 0) gather_kernel<0><<<gatherBlocks, 256>>>(n);
        else gather_kernel<1><<<gatherBlocks, 256>>>(n);
        mlp_kernel<<<MLP_GRID, 512, SMEM_BYTES>>>(l, b1 + l * 128, b2 + l * 128,
                                                  gamma + l * 128, beta + l * 128, n);
    }
    bnfinal_kernel<<<ewBlocks, 256>>>((float*)d_out, n);
}

// round 17
// speedup vs baseline: 1.1743x; 1.0734x over previous
#include <cuda_runtime.h>
#include <cuda_bf16.h>
#include <cuda_fp16.h>
#include <cstdint>

#define NNODES 100000
#define NEDGES 800000
#define DIM 128

// ---------------- static scratch ----------------
__device__ __align__(16) __half g_zh[(size_t)NNODES * DIM];             // z staged fp16
__device__ __align__(16) __half g_hx[(size_t)NNODES * DIM];             // h staged fp16 (x, then BN'd z)
__device__ __align__(16) __nv_bfloat16 g_wt[6 * 128 * 256];             // [l*2+m][n][256] hi|lo
__device__ float g_stats[256];      // colsum|colsumsq; zeroed by last mlp CTA each layer
__device__ float g_bnScale[128];
__device__ float g_bnShift[128];
__device__ int g_mlpDone;           // last-CTA election counter (reset each layer)
__device__ int g_deg[NNODES];
__device__ int g_rowptr[NNODES];
__device__ int g_cursor[NNODES];
__device__ int g_eidx[NEDGES];
__device__ int g_part[512];
__device__ int g_is64;

__device__ __forceinline__ int load_idx(const void* ei, int is64, size_t pos) {
    if (is64) return (int)((const long long*)ei)[pos];
    return ((const int*)ei)[pos];
}

// ---------------- weight prep + edge-dtype detection (block 0) ----------------
__global__ void wprep_kernel(const float* __restrict__ W1, const float* __restrict__ W2,
                             const void* __restrict__ ei, int E, int n) {
    if (blockIdx.x == 0) {
        __shared__ int bad;
        if (threadIdx.x == 0) bad = 0;
        __syncthreads();
        const long long* p = (const long long*)ei;
        int m = (E < 4096) ? E : 4096;
        for (int i = threadIdx.x; i < m; i += blockDim.x) {
            long long v = p[i];
            if (v < 0 || v >= (long long)n) bad = 1;
        }
        __syncthreads();
        if (threadIdx.x == 0) g_is64 = bad ? 0 : 1;
    }
    int idx = blockIdx.x * blockDim.x + threadIdx.x;
    if (idx >= 3 * 2 * 128 * 128) return;
    int nn = idx & 127;
    int k = (idx >> 7) & 127;
    int m2 = (idx >> 14) & 1;
    int l = idx >> 15;
    const float* W = m2 ? W2 : W1;
    float v = W[((size_t)l * 128 + k) * 128 + nn];
    __nv_bfloat16 hi = __float2bfloat16(v);
    __nv_bfloat16 lo = __float2bfloat16(v - __bfloat162float(hi));
    size_t base = ((size_t)(l * 2 + m2) * 128 + nn) * 256;
    g_wt[base + k] = hi;
    g_wt[base + 128 + k] = lo;
}

// ---------------- x -> fp16 staging; zero degree counters ----------------
__global__ void prepx_kernel(const float* __restrict__ x, int n) {
    int idx = blockIdx.x * blockDim.x + threadIdx.x;
    if (idx < n) g_deg[idx] = 0;
    if (idx >= n * 32) return;
    int row = idx >> 5;
    int c4 = (idx & 31) * 4;
    float4 v = *reinterpret_cast<const float4*>(x + (size_t)row * DIM + c4);
    __half2 a = __floats2half2_rn(v.x, v.y);
    __half2 b = __floats2half2_rn(v.z, v.w);
    *reinterpret_cast<__half2*>(g_hx + (size_t)row * DIM + c4) = a;
    *reinterpret_cast<__half2*>(g_hx + (size_t)row * DIM + c4 + 2) = b;
}

// ---------------- CSR build ----------------
__global__ void hist_kernel(const void* __restrict__ ei, int E, int n) {
    int e = blockIdx.x * blockDim.x + threadIdx.x;
    if (e >= E) return;
    int d = load_idx(ei, g_is64, (size_t)E + e);
    if ((unsigned)d < (unsigned)n) atomicAdd(&g_deg[d], 1);
}

__global__ void scanA_kernel(int n) {
    __shared__ int s[512];
    int tid = threadIdx.x;
    int i = blockIdx.x * 512 + tid;
    s[tid] = (i < n) ? g_deg[i] : 0;
    __syncthreads();
    for (int off = 256; off > 0; off >>= 1) {
        if (tid < off) s[tid] += s[tid + off];
        __syncthreads();
    }
    if (tid == 0) g_part[blockIdx.x] = s[0];
}

__global__ void scanB_kernel(int nb) {
    __shared__ int s[512];
    int tid = threadIdx.x;
    int v = (tid < nb) ? g_part[tid] : 0;
    s[tid] = v;
    __syncthreads();
    for (int off = 1; off < 512; off <<= 1) {
        int tv = (tid >= off) ? s[tid - off] : 0;
        __syncthreads();
        s[tid] += tv;
        __syncthreads();
    }
    if (tid < nb) g_part[tid] = s[tid] - v;   // exclusive
}

__global__ void scanC_kernel(int n) {
    __shared__ int s[512];
    int tid = threadIdx.x;
    int i = blockIdx.x * 512 + tid;
    int v = (i < n) ? g_deg[i] : 0;
    s[tid] = v;
    __syncthreads();
    for (int off = 1; off < 512; off <<= 1) {
        int tv = (tid >= off) ? s[tid - off] : 0;
        __syncthreads();
        s[tid] += tv;
        __syncthreads();
    }
    if (i < n) {
        int start = g_part[blockIdx.x] + s[tid] - v;
        g_rowptr[i] = start;
        g_cursor[i] = start;
    }
}

__global__ void fill_kernel(const void* __restrict__ ei, int E, int n) {
    int e = blockIdx.x * blockDim.x + threadIdx.x;
    if (e >= E) return;
    int is64 = g_is64;
    int s = load_idx(ei, is64, (size_t)e);
    int d = load_idx(ei, is64, (size_t)E + e);
    if ((unsigned)d >= (unsigned)n || (unsigned)s >= (unsigned)n) return;
    int pos = atomicAdd(&g_cursor[d], 1);
    g_eidx[pos] = s;
}

// ---------------- persistent fused GATHER+MLP — 4 decoupled row-group pipelines ----------------
// Per tile, each 128-thread row-group: (1) gathers its 16 rows (8 threads/row,
// 16 cols/thread, fp32 reg accumulation of fp16 h rows) and writes the bf16 hi/lo
// split straight into the smem A tile; (2) GEMM1; (3) epi0 (bias+relu+split -> A);
// (4) GEMM2; (5) epi1 (bias -> g_zh + stats). Group-local named barriers only —
// the 4 groups pipeline independently, hiding gather latency under MMA.
#define ASTRIDE 264
#define WBYTES (128 * ASTRIDE * 2)
#define ABYTES (64 * ASTRIDE * 2)
#define SMEM_BYTES (2 * WBYTES + ABYTES)
#define MLP_GRID 148

__device__ __forceinline__ void mma_bf16(float d[4], const uint32_t a[4], const uint32_t b0, const uint32_t b1) {
    asm volatile(
        "mma.sync.aligned.m16n8k16.row.col.f32.bf16.bf16.f32 "
        "{%0,%1,%2,%3}, {%4,%5,%6,%7}, {%8,%9}, {%0,%1,%2,%3};\n"
        : "+f"(d[0]), "+f"(d[1]), "+f"(d[2]), "+f"(d[3])
        : "r"(a[0]), "r"(a[1]), "r"(a[2]), "r"(a[3]), "r"(b0), "r"(b1));
}

__device__ __forceinline__ void ldsm_x4(uint32_t r[4], uint32_t addr) {
    asm volatile("ldmatrix.sync.aligned.m8n8.x4.shared.b16 {%0,%1,%2,%3}, [%4];\n"
                 : "=r"(r[0]), "=r"(r[1]), "=r"(r[2]), "=r"(r[3]) : "r"(addr));
}

__device__ __forceinline__ void cpa16(uint32_t dst, const void* src) {
    asm volatile("cp.async.ca.shared.global [%0], [%1], 16;\n" :: "r"(dst), "l"(src));
}

__device__ __forceinline__ void accum16(float* acc, uint4 a, uint4 b) {
    const __half2* ha = reinterpret_cast<const __half2*>(&a);
    const __half2* hb = reinterpret_cast<const __half2*>(&b);
#pragma unroll
    for (int q = 0; q < 4; q++) {
        float2 f = __half22float2(ha[q]);
        acc[2 * q] += f.x; acc[2 * q + 1] += f.y;
    }
#pragma unroll
    for (int q = 0; q < 4; q++) {
        float2 f = __half22float2(hb[q]);
        acc[8 + 2 * q] += f.x; acc[8 + 2 * q + 1] += f.y;
    }
}

// fused 3-pass k-loop; warp tile 16x32: 6 LDSM + 12 MMA per k-step
__device__ __forceinline__ void gemm_phase(uint32_t aAddr, const uint32_t bAddr0, const uint32_t bAddr1,
                                           float acc[4][4]) {
    uint32_t bA[2] = {bAddr0, bAddr1};
#pragma unroll
    for (int kk = 0; kk < 128; kk += 16) {
        uint32_t ah[4], al[4], bh[2][4], bl[2][4];
        ldsm_x4(ah, aAddr + kk * 2);
        ldsm_x4(al, aAddr + 256 + kk * 2);
#pragma unroll
        for (int np = 0; np < 2; np++) {
            ldsm_x4(bh[np], bA[np] + kk * 2);
            ldsm_x4(bl[np], bA[np] + 256 + kk * 2);
        }
#pragma unroll
        for (int nt = 0; nt < 4; nt++)
            mma_bf16(acc[nt], ah, bh[nt >> 1][(nt & 1) * 2], bh[nt >> 1][(nt & 1) * 2 + 1]);
#pragma unroll
        for (int nt = 0; nt < 4; nt++)
            mma_bf16(acc[nt], ah, bl[nt >> 1][(nt & 1) * 2], bl[nt >> 1][(nt & 1) * 2 + 1]);
#pragma unroll
        for (int nt = 0; nt < 4; nt++)
            mma_bf16(acc[nt], al, bh[nt >> 1][(nt & 1) * 2], bh[nt >> 1][(nt & 1) * 2 + 1]);
    }
}

__global__ __launch_bounds__(512, 1) void mlp_kernel(int layer, const float* __restrict__ b1,
                                                     const float* __restrict__ b2,
                                                     const float* __restrict__ gamma,
                                                     const float* __restrict__ beta, int n) {
    extern __shared__ char smem_raw[];
    uint32_t sW1 = (uint32_t)__cvta_generic_to_shared(smem_raw);
    uint32_t sW2 = sW1 + WBYTES;
    uint32_t sA = sW2 + WBYTES;
    __shared__ float sb1[128], sb2[128], ssum[128], ssq[128];
    __shared__ int sLast;

    const __nv_bfloat16* __restrict__ W1g = g_wt + (size_t)(layer * 2 + 0) * 128 * 256;
    const __nv_bfloat16* __restrict__ W2g = g_wt + (size_t)(layer * 2 + 1) * 128 * 256;

    int tid = threadIdx.x;
    int numTiles = (n + 63) / 64;

    int warp = tid >> 5, lane = tid & 31;
    int wm = warp & 3, wn = warp >> 2;          // 4(M) x 4(N) warp grid
    int mBase = wm * 16, nBase = wn * 32;       // warp tile 16 x 32
    int g = lane >> 2, t = lane & 3;
    int barid = 1 + wm;
    int gtid = (wn << 5) | lane;                // 0..127 within row-group
    int rloc = gtid >> 3;                       // 0..15: row within group
    int sub = gtid & 7;                         // 8 threads per row, 16 cols each

    for (int i = tid; i < 4096; i += 512) {
        int r = i >> 5, s = i & 31;
        cpa16(sW1 + (r * ASTRIDE + s * 8) * 2, W1g + (size_t)r * 256 + s * 8);
        cpa16(sW2 + (r * ASTRIDE + s * 8) * 2, W2g + (size_t)r * 256 + s * 8);
    }
    asm volatile("cp.async.commit_group;\n");
    if (tid < 128) { sb1[tid] = b1[tid]; sb2[tid] = b2[tid]; ssum[tid] = 0.f; ssq[tid] = 0.f; }
    asm volatile("cp.async.wait_group 0;\n" ::: "memory");
    __syncthreads();

    uint32_t aOff = (uint32_t)(((mBase + (lane & 15)) * ASTRIDE + (lane >> 4) * 8) * 2);
    uint32_t bOff0, bOff1;
    {
        int q = lane >> 3, rw = lane & 7;
        int rowoff = (q >> 1) * 8 + rw, coloff = (q & 1) * 8;
        bOff0 = (uint32_t)(((nBase + 0 + rowoff) * ASTRIDE + coloff) * 2);
        bOff1 = (uint32_t)(((nBase + 16 + rowoff) * ASTRIDE + coloff) * 2);
    }
    // gather store base: this thread's 16 cols of its row in the A tile
    uint32_t gstore = sA + (uint32_t)(((mBase + rloc) * ASTRIDE + sub * 16) * 2);

    float cs[4][2], cq[4][2];
#pragma unroll
    for (int nt = 0; nt < 4; nt++) { cs[nt][0] = cs[nt][1] = 0.f; cq[nt][0] = cq[nt][1] = 0.f; }

    for (int tile = blockIdx.x; tile < numTiles; tile += MLP_GRID) {
        // ---- phase 0: gather this group's 16 rows into registers, split -> sA ----
        {
            float acc[16];
#pragma unroll
            for (int k = 0; k < 16; k++) acc[k] = 0.f;
            int grow = tile * 64 + mBase + rloc;
            if (grow < n) {
                const __half* __restrict__ base = g_hx;
                const __half* selfp = base + (size_t)grow * DIM + sub * 16;
                uint4 sa = *reinterpret_cast<const uint4*>(selfp);
                uint4 sb = *reinterpret_cast<const uint4*>(selfp + 8);
                accum16(acc, sa, sb);
                int j = g_rowptr[grow];
                int end = j + g_deg[grow];
                for (; j + 4 <= end; j += 4) {
                    int s0 = g_eidx[j], s1 = g_eidx[j + 1], s2 = g_eidx[j + 2], s3 = g_eidx[j + 3];
                    const __half* r0 = base + (size_t)s0 * DIM + sub * 16;
                    const __half* r1 = base + (size_t)s1 * DIM + sub * 16;
                    const __half* r2 = base + (size_t)s2 * DIM + sub * 16;
                    const __half* r3 = base + (size_t)s3 * DIM + sub * 16;
                    uint4 a0 = *reinterpret_cast<const uint4*>(r0);
                    uint4 b0 = *reinterpret_cast<const uint4*>(r0 + 8);
                    uint4 a1 = *reinterpret_cast<const uint4*>(r1);
                    uint4 b1v = *reinterpret_cast<const uint4*>(r1 + 8);
                    uint4 a2 = *reinterpret_cast<const uint4*>(r2);
                    uint4 b2v = *reinterpret_cast<const uint4*>(r2 + 8);
                    uint4 a3 = *reinterpret_cast<const uint4*>(r3);
                    uint4 b3 = *reinterpret_cast<const uint4*>(r3 + 8);
                    accum16(acc, a0, b0);
                    accum16(acc, a1, b1v);
                    accum16(acc, a2, b2v);
                    accum16(acc, a3, b3);
                }
                for (; j < end; j++) {
                    int s = g_eidx[j];
                    const __half* r0 = base + (size_t)s * DIM + sub * 16;
                    uint4 a0 = *reinterpret_cast<const uint4*>(r0);
                    uint4 b0 = *reinterpret_cast<const uint4*>(r0 + 8);
                    accum16(acc, a0, b0);
                }
            }
            // hi/lo split -> smem (hi at col, lo at col+128 => +256 bytes)
            uint32_t hw[8], lw[8];
#pragma unroll
            for (int k = 0; k < 16; k += 2) {
                __nv_bfloat16 h0 = __float2bfloat16(acc[k]);
                __nv_bfloat16 h1 = __float2bfloat16(acc[k + 1]);
                __nv_bfloat16 l0 = __float2bfloat16(acc[k] - __bfloat162float(h0));
                __nv_bfloat16 l1 = __float2bfloat16(acc[k + 1] - __bfloat162float(h1));
                union { __nv_bfloat162 b; uint32_t u; } HP, LP;
                HP.b.x = h0; HP.b.y = h1; LP.b.x = l0; LP.b.y = l1;
                hw[k >> 1] = HP.u; lw[k >> 1] = LP.u;
            }
#pragma unroll
            for (int w = 0; w < 8; w++) {
                asm volatile("st.shared.b32 [%0], %1;" :: "r"(gstore + w * 4), "r"(hw[w]));
                asm volatile("st.shared.b32 [%0], %1;" :: "r"(gstore + 256 + w * 4), "r"(lw[w]));
            }
        }
        asm volatile("bar.sync %0, 128;" :: "r"(barid) : "memory");

        // ---- GEMM 1 ----
        float acc[4][4];
#pragma unroll
        for (int b = 0; b < 4; b++)
#pragma unroll
            for (int c = 0; c < 4; c++) acc[b][c] = 0.f;
        gemm_phase(sA + aOff, sW1 + bOff0, sW1 + bOff1, acc);
        asm volatile("bar.sync %0, 128;" :: "r"(barid) : "memory");

        // epi 0: bias1 + relu + hi/lo split -> this group's rows of sA
#pragma unroll
        for (int i = 0; i < 2; i++) {
            int lrow = mBase + g + i * 8;
#pragma unroll
            for (int nt = 0; nt < 4; nt++) {
                int col = nBase + nt * 8 + t * 2;
                float v0 = fmaxf(acc[nt][i * 2 + 0] + sb1[col], 0.f);
                float v1 = fmaxf(acc[nt][i * 2 + 1] + sb1[col + 1], 0.f);
                __nv_bfloat16 h0 = __float2bfloat16(v0);
                __nv_bfloat16 h1 = __float2bfloat16(v1);
                __nv_bfloat16 l0 = __float2bfloat16(v0 - __bfloat162float(h0));
                __nv_bfloat16 l1 = __float2bfloat16(v1 - __bfloat162float(h1));
                union { __nv_bfloat162 b; uint32_t u; } HP, LP;
                HP.b.x = h0; HP.b.y = h1; LP.b.x = l0; LP.b.y = l1;
                uint32_t op = sA + (uint32_t)((lrow * ASTRIDE + col) * 2);
                asm volatile("st.shared.b32 [%0], %1;" :: "r"(op), "r"(HP.u));
                asm volatile("st.shared.b32 [%0], %1;" :: "r"(op + 256), "r"(LP.u));
            }
        }
        asm volatile("bar.sync %0, 128;" :: "r"(barid) : "memory");

        // ---- GEMM 2 ----
#pragma unroll
        for (int b = 0; b < 4; b++)
#pragma unroll
            for (int c = 0; c < 4; c++) acc[b][c] = 0.f;
        gemm_phase(sA + aOff, sW2 + bOff0, sW2 + bOff1, acc);

        // epi 1: bias2 -> g_zh (fp16) + register stats (fp32, unrounded)
        int rowBase = tile * 64;
#pragma unroll
        for (int i = 0; i < 2; i++) {
            int row = rowBase + mBase + g + i * 8;
            if (row >= n) continue;
#pragma unroll
            for (int nt = 0; nt < 4; nt++) {
                int col = nBase + nt * 8 + t * 2;
                float v0 = acc[nt][i * 2 + 0] + sb2[col];
                float v1 = acc[nt][i * 2 + 1] + sb2[col + 1];
                *reinterpret_cast<__half2*>(g_zh + (size_t)row * DIM + col) = __floats2half2_rn(v0, v1);
                cs[nt][0] += v0; cq[nt][0] += v0 * v0;
                cs[nt][1] += v1; cq[nt][1] += v1 * v1;
            }
        }
        // protect sA: GEMM2 reads done before next tile's gather overwrites
        asm volatile("bar.sync %0, 128;" :: "r"(barid) : "memory");
    }

    // ---- stats reduction + last-CTA BN finalize ----
    __syncthreads();
#pragma unroll
    for (int nt = 0; nt < 4; nt++) {
#pragma unroll
        for (int j = 0; j < 2; j++) {
            int col = nBase + nt * 8 + t * 2 + j;
            atomicAdd(&ssum[col], cs[nt][j]);
            atomicAdd(&ssq[col], cq[nt][j]);
        }
    }
    __syncthreads();
    if (tid < 128) {
        atomicAdd(&g_stats[tid], ssum[tid]);
        atomicAdd(&g_stats[128 + tid], ssq[tid]);
    }
    __threadfence();
    __syncthreads();
    if (tid == 0) {
        int prev = atomicAdd(&g_mlpDone, 1);
        sLast = (prev == MLP_GRID - 1) ? 1 : 0;
    }
    __syncthreads();
    if (sLast) {
        if (tid < 128) {
            int c = tid;
            float invN = 1.f / (float)n;
            float mean = g_stats[c] * invN;
            float var = g_stats[128 + c] * invN - mean * mean;
            float rstd = rsqrtf(fmaxf(var, 0.f) + 1e-5f);
            float scale = gamma[c] * rstd;
            g_bnScale[c] = scale;
            g_bnShift[c] = beta[c] - mean * scale;
            g_stats[c] = 0.f;
            g_stats[128 + c] = 0.f;
        }
        if (tid == 0) g_mlpDone = 0;
    }
}

// ---------------- BN+ReLU apply: z (fp16) -> h (fp16) for next layer's gather ----
__global__ void bnapply_kernel(int n) {
    int idx = blockIdx.x * blockDim.x + threadIdx.x;
    if (idx >= n * 32) return;
    int row = idx >> 5;
    int c4 = (idx & 31) * 4;
    const __half2* zp = reinterpret_cast<const __half2*>(g_zh + (size_t)row * DIM + c4);
    float2 z01 = __half22float2(zp[0]);
    float2 z23 = __half22float2(zp[1]);
    float4 sc = *reinterpret_cast<const float4*>(g_bnScale + c4);
    float4 sh = *reinterpret_cast<const float4*>(g_bnShift + c4);
    __half2 o01 = __floats2half2_rn(fmaxf(z01.x * sc.x + sh.x, 0.f), fmaxf(z01.y * sc.y + sh.y, 0.f));
    __half2 o23 = __floats2half2_rn(fmaxf(z23.x * sc.z + sh.z, 0.f), fmaxf(z23.y * sc.w + sh.w, 0.f));
    __half2* op = reinterpret_cast<__half2*>(g_hx + (size_t)row * DIM + c4);
    op[0] = o01;
    op[1] = o23;
}

// ---------------- final BN+ReLU -> d_out ----------------
__global__ void bnfinal_kernel(float* __restrict__ dout, int n) {
    int idx = blockIdx.x * blockDim.x + threadIdx.x;
    if (idx >= n * 32) return;
    int row = idx >> 5;
    int c4 = (idx & 31) * 4;
    const __half2* zp = reinterpret_cast<const __half2*>(g_zh + (size_t)row * DIM + c4);
    float2 z01 = __half22float2(zp[0]);
    float2 z23 = __half22float2(zp[1]);
    float4 sc = *reinterpret_cast<const float4*>(g_bnScale + c4);
    float4 sh = *reinterpret_cast<const float4*>(g_bnShift + c4);
    float4 o;
    o.x = fmaxf(z01.x * sc.x + sh.x, 0.f);
    o.y = fmaxf(z01.y * sc.y + sh.y, 0.f);
    o.z = fmaxf(z23.x * sc.z + sh.z, 0.f);
    o.w = fmaxf(z23.y * sc.w + sh.w, 0.f);
    *reinterpret_cast<float4*>(dout + (size_t)row * DIM + c4) = o;
}

// ---------------- host launcher ----------------
extern "C" void kernel_launch(void* const* d_in, const int* in_sizes, int n_in,
                              void* d_out, int out_size) {
    const float* x = (const float*)d_in[0];
    const void* ei = d_in[1];
    const float* W1 = (const float*)d_in[2];
    const float* b1 = (const float*)d_in[3];
    const float* W2 = (const float*)d_in[4];
    const float* b2 = (const float*)d_in[5];
    const float* gamma = (const float*)d_in[6];
    const float* beta = (const float*)d_in[7];
    (void)n_in; (void)out_size;

    int n = in_sizes[0] / DIM;
    int E = in_sizes[1] / 2;
    if (n > NNODES) n = NNODES;
    if (E > NEDGES) E = NEDGES;

    cudaFuncSetAttribute(mlp_kernel, cudaFuncAttributeMaxDynamicSharedMemorySize, SMEM_BYTES);

    int ewBlocks = (n * 32 + 255) / 256;

    wprep_kernel<<<(3 * 2 * 128 * 128 + 255) / 256, 256>>>(W1, W2, ei, E, n);
    prepx_kernel<<<ewBlocks, 256>>>(x, n);
    hist_kernel<<<(E + 255) / 256, 256>>>(ei, E, n);
    int nsb = (n + 511) / 512;
    scanA_kernel<<<nsb, 512>>>(n);
    scanB_kernel<<<1, 512>>>(nsb);
    scanC_kernel<<<nsb, 512>>>(n);
    fill_kernel<<<(E + 255) / 256, 256>>>(ei, E, n);

    for (int l = 0; l < 3; l++) {
        if (l > 0) bnapply_kernel<<<ewBlocks, 256>>>(n);
        mlp_kernel<<<MLP_GRID, 512, SMEM_BYTES>>>(l, b1 + l * 128, b2 + l * 128,
                                                  gamma + l * 128, beta + l * 128, n);
    }
    bnfinal_kernel<<<ewBlocks, 256>>>((float*)d_out, n);
}